// round 1
// baseline (speedup 1.0000x reference)
#include <cuda_runtime.h>
#include <math.h>

// Problem constants
#define BB 32
#define TT 1024
#define HH 512
#define VV 1024
#define SS 128
#define LL 257          // 2*S + 1
#define NEGV (-1e30f)

// Scratch (device globals: allocation-free per harness rules)
__device__ float g_h[(size_t)BB * TT * HH];        // 64 MB  : tanh(X@W1+b1)
__device__ float g_logits[(size_t)BB * TT * VV];   // 128 MB : h@W2+b2
__device__ float g_lp[(size_t)BB * TT * LL];       // 34 MB  : log_probs gathered at ext labels

__device__ __forceinline__ float logaddf(float a, float b) {
    float m = fmaxf(a, b);
    float d = fabsf(a - b);
    return m + log1pf(expf(-d));
}

// ---------------------------------------------------------------------------
// Tiled fp32 GEMM: C[M,N] = act(A[M,K] @ W[K,N] + bias), 128x128x8 tiles,
// 256 threads, 8x8 micro-tile per thread. M=32768 fixed; N,K compile-time.
// ---------------------------------------------------------------------------
template <int N, int K, int TANH>
__device__ __forceinline__ void gemm_body(const float* __restrict__ A,
                                          const float* __restrict__ W,
                                          const float* __restrict__ bias,
                                          float* __restrict__ C) {
    __shared__ float As[8][132];   // padded: conflict-free transposed stores
    __shared__ float Bs[8][128];

    const int tid  = threadIdx.x;
    const int tx   = tid & 15;
    const int ty   = tid >> 4;
    const int row0 = blockIdx.y * 128;
    const int col0 = blockIdx.x * 128;

    // A tile load map: 128 rows x 8 k-cols, one float4 per thread
    const int arow = tid >> 1;
    const int acol = (tid & 1) << 2;
    // B tile load map: 8 k-rows x 128 cols, one float4 per thread
    const int brow = tid >> 5;
    const int bcol = (tid & 31) << 2;

    const float* Aptr = A + (size_t)(row0 + arow) * K + acol;
    const float* Wptr = W + (size_t)brow * N + col0 + bcol;

    float acc[8][8];
#pragma unroll
    for (int i = 0; i < 8; i++)
#pragma unroll
        for (int j = 0; j < 8; j++) acc[i][j] = 0.f;

    for (int k0 = 0; k0 < K; k0 += 8) {
        float4 av = *reinterpret_cast<const float4*>(Aptr + k0);
        float4 bv = *reinterpret_cast<const float4*>(Wptr + (size_t)k0 * N);
        As[acol + 0][arow] = av.x;
        As[acol + 1][arow] = av.y;
        As[acol + 2][arow] = av.z;
        As[acol + 3][arow] = av.w;
        *reinterpret_cast<float4*>(&Bs[brow][bcol]) = bv;
        __syncthreads();

#pragma unroll
        for (int kk = 0; kk < 8; kk++) {
            float4 a0 = *reinterpret_cast<const float4*>(&As[kk][ty * 8]);
            float4 a1 = *reinterpret_cast<const float4*>(&As[kk][ty * 8 + 4]);
            float4 b0 = *reinterpret_cast<const float4*>(&Bs[kk][tx * 8]);
            float4 b1 = *reinterpret_cast<const float4*>(&Bs[kk][tx * 8 + 4]);
            float a[8] = {a0.x, a0.y, a0.z, a0.w, a1.x, a1.y, a1.z, a1.w};
            float b[8] = {b0.x, b0.y, b0.z, b0.w, b1.x, b1.y, b1.z, b1.w};
#pragma unroll
            for (int i = 0; i < 8; i++)
#pragma unroll
                for (int j = 0; j < 8; j++)
                    acc[i][j] = fmaf(a[i], b[j], acc[i][j]);
        }
        __syncthreads();
    }

#pragma unroll
    for (int i = 0; i < 8; i++) {
        const int r  = row0 + ty * 8 + i;
        float* cp    = C + (size_t)r * N + col0 + tx * 8;
#pragma unroll
        for (int j = 0; j < 8; j += 4) {
            float4 v;
            v.x = acc[i][j + 0] + bias[col0 + tx * 8 + j + 0];
            v.y = acc[i][j + 1] + bias[col0 + tx * 8 + j + 1];
            v.z = acc[i][j + 2] + bias[col0 + tx * 8 + j + 2];
            v.w = acc[i][j + 3] + bias[col0 + tx * 8 + j + 3];
            if (TANH) {
                v.x = tanhf(v.x); v.y = tanhf(v.y);
                v.z = tanhf(v.z); v.w = tanhf(v.w);
            }
            *reinterpret_cast<float4*>(cp + j) = v;
        }
    }
}

__global__ void __launch_bounds__(256)
gemm1_kernel(const float* __restrict__ X, const float* __restrict__ W1,
             const float* __restrict__ b1) {
    gemm_body<HH, HH, 1>(X, W1, b1, g_h);
}

__global__ void __launch_bounds__(256)
gemm2_kernel(const float* __restrict__ W2, const float* __restrict__ b2) {
    gemm_body<VV, HH, 0>(g_h, W2, b2, g_logits);
}

// ---------------------------------------------------------------------------
// Per-row logsumexp over V=1024 logits + gather log-prob at extended labels.
// One block per (b,t) row; writes lp_ext[b][t][s], s in [0,257).
// ---------------------------------------------------------------------------
__global__ void __launch_bounds__(256)
lse_gather_kernel(const int* __restrict__ targets) {
    const int row = blockIdx.x;        // b*T + t
    const int b   = row >> 10;         // T = 1024
    const float* lr = g_logits + (size_t)row * VV;
    const int tid = threadIdx.x;

    __shared__ float red[256];

    float m = -INFINITY;
    for (int i = tid; i < VV; i += 256) m = fmaxf(m, lr[i]);
    red[tid] = m;
    __syncthreads();
#pragma unroll
    for (int s = 128; s > 0; s >>= 1) {
        if (tid < s) red[tid] = fmaxf(red[tid], red[tid + s]);
        __syncthreads();
    }
    m = red[0];
    __syncthreads();

    float sum = 0.f;
    for (int i = tid; i < VV; i += 256) sum += expf(lr[i] - m);
    red[tid] = sum;
    __syncthreads();
#pragma unroll
    for (int s = 128; s > 0; s >>= 1) {
        if (tid < s) red[tid] += red[tid + s];
        __syncthreads();
    }
    const float lse = m + logf(red[0]);

    float* lpr = g_lp + (size_t)row * LL;
    const int* tg = targets + b * SS;
    for (int s = tid; s < LL; s += 256) {
        const int lab = (s & 1) ? tg[s >> 1] : 0;   // blank = PAD = 0
        lpr[s] = lr[lab] - lse;
    }
}

// ---------------------------------------------------------------------------
// CTC forward scan: one block per batch element, 257 active lanes, T steps.
// Double-buffered alpha in shared mem, 1-deep prefetch of lp_ext[t+1].
// ---------------------------------------------------------------------------
__global__ void __launch_bounds__(288)
ctc_kernel(const int* __restrict__ targets, const int* __restrict__ input_lengths,
           float* __restrict__ out) {
    const int b = blockIdx.x;
    const int s = threadIdx.x;
    const bool active = s < LL;

    __shared__ float buf[2][LL + 2];

    const int* tg = targets + b * SS;
    const float* lpb = g_lp + (size_t)b * TT * LL;
    const int Tlen = input_lengths[b];

    bool skip = false;
    if (active && (s & 1) && s >= 3)
        skip = (tg[s >> 1] != tg[(s >> 1) - 1]);

    if (s < 2) { buf[0][s] = NEGV; buf[1][s] = NEGV; }
    if (active) buf[0][s + 2] = (s < 2) ? lpb[s] : NEGV;
    __syncthreads();

    float lp_next = 0.f;
    if (active && Tlen > 1) lp_next = lpb[(size_t)LL + s];

    for (int t = 1; t < Tlen; ++t) {
        const int pc = (t - 1) & 1, nc = t & 1;
        const float lpc = lp_next;
        if (active) {
            const int tn = (t + 1 < Tlen) ? t + 1 : t;
            lp_next = lpb[(size_t)tn * LL + s];   // prefetch next step
            float v = logaddf(buf[pc][s + 2], buf[pc][s + 1]);
            if (skip) v = logaddf(v, buf[pc][s]);
            buf[nc][s + 2] = v + lpc;
        }
        __syncthreads();
    }

    if (s == 0) {
        int sb = 0;
#pragma unroll 8
        for (int i = 0; i < SS; i++) sb += (tg[i] != 0);
        const int fin = (Tlen - 1) & 1;
        const float e1 = buf[fin][2 + 2 * sb - 1];
        const float e2 = buf[fin][2 + 2 * sb];
        out[b] = -logaddf(e1, e2) / (float)sb;
    }
}

// ---------------------------------------------------------------------------
extern "C" void kernel_launch(void* const* d_in, const int* in_sizes, int n_in,
                              void* d_out, int out_size) {
    const int*   targets = (const int*)  d_in[0];   // [32,128] int32
    const float* X       = (const float*)d_in[1];   // [32,1024,512]
    const int*   ilen    = (const int*)  d_in[2];   // [32]
    const float* W1      = (const float*)d_in[3];   // [512,512]
    const float* b1      = (const float*)d_in[4];   // [512]
    const float* W2      = (const float*)d_in[5];   // [512,1024]
    const float* b2      = (const float*)d_in[6];   // [1024]
    float*       out     = (float*)d_out;           // [32]

    const int M = BB * TT;  // 32768

    dim3 g1(HH / 128, M / 128);   // (4, 256)
    gemm1_kernel<<<g1, 256>>>(X, W1, b1);

    dim3 g2(VV / 128, M / 128);   // (8, 256)
    gemm2_kernel<<<g2, 256>>>(W2, b2);

    lse_gather_kernel<<<M, 256>>>(targets);

    ctc_kernel<<<BB, 288>>>(targets, ilen, out);
}

// round 2
// speedup vs baseline: 1.6250x; 1.6250x over previous
#include <cuda_runtime.h>
#include <cuda_bf16.h>
#include <math.h>

// Problem constants
#define BB 32
#define TT 1024
#define HH 512
#define VV 1024
#define SS 128
#define LL 257          // 2*S + 1
#define NEGV (-1e30f)

// Scratch (device globals: allocation-free per harness rules)
__device__ __nv_bfloat16 g_Xb[(size_t)BB * TT * HH];   // 32 MB  : X in bf16
__device__ __nv_bfloat16 g_W1b[(size_t)HH * HH];       // 0.5 MB
__device__ __nv_bfloat16 g_W2b[(size_t)HH * VV];       // 1 MB
__device__ __nv_bfloat16 g_hb[(size_t)BB * TT * HH];   // 32 MB  : tanh(X@W1+b1) bf16
__device__ float g_logits[(size_t)BB * TT * VV];       // 128 MB : h@W2+b2
__device__ float g_lp[(size_t)BB * TT * LL];           // 34 MB  : log-probs at ext labels

// ---------------------------------------------------------------------------
// float -> bf16 conversion (vectorized)
// ---------------------------------------------------------------------------
__global__ void __launch_bounds__(256)
f2bf_kernel(const float* __restrict__ in, __nv_bfloat16* __restrict__ out, int n) {
    int i = (blockIdx.x * 256 + threadIdx.x) * 4;
    if (i < n) {
        float4 v = *reinterpret_cast<const float4*>(in + i);
        __nv_bfloat162 p0 = __floats2bfloat162_rn(v.x, v.y);
        __nv_bfloat162 p1 = __floats2bfloat162_rn(v.z, v.w);
        *reinterpret_cast<__nv_bfloat162*>(out + i)     = p0;
        *reinterpret_cast<__nv_bfloat162*>(out + i + 2) = p1;
    }
}

// ---------------------------------------------------------------------------
// bf16 tensor-core GEMM: C[M,N] = act(A[M,K] @ W[K,N] + bias)
// 128x128 block tile, BK=32, 256 threads (8 warps, 4x2), warp tile 32x64,
// mma.sync.m16n8k16 bf16 -> f32 accum.
// ---------------------------------------------------------------------------
__device__ __forceinline__ void mma16816(float* c, const unsigned* a, const unsigned* b) {
    asm volatile(
        "mma.sync.aligned.m16n8k16.row.col.f32.bf16.bf16.f32 "
        "{%0,%1,%2,%3}, {%4,%5,%6,%7}, {%8,%9}, {%0,%1,%2,%3};"
        : "+f"(c[0]), "+f"(c[1]), "+f"(c[2]), "+f"(c[3])
        : "r"(a[0]), "r"(a[1]), "r"(a[2]), "r"(a[3]), "r"(b[0]), "r"(b[1]));
}

#define ASTRIDE 40   // halves; 80B rows -> conflict-free A-frag LDS
#define BSTRIDE 38   // halves; 76B rows (19 banks, odd) -> near-conflict-free B-frag LDS

template <int N, int K, int TANH>
__device__ __forceinline__ void mma_gemm_body(const __nv_bfloat16* __restrict__ A,
                                              const __nv_bfloat16* __restrict__ W,
                                              const float* __restrict__ bias,
                                              __nv_bfloat16* __restrict__ Cb,
                                              float* __restrict__ Cf) {
    __shared__ __nv_bfloat16 As[128][ASTRIDE];
    __shared__ __nv_bfloat16 Bs[128][BSTRIDE];   // B^T tile: Bs[n][k]

    const int tid  = threadIdx.x;
    const int lane = tid & 31;
    const int warp = tid >> 5;
    const int wm   = warp & 3;      // 0..3 -> m offset wm*32
    const int wn   = warp >> 2;     // 0..1 -> n offset wn*64
    const int gid  = lane >> 2;
    const int tig  = lane & 3;

    const int row0 = blockIdx.y * 128;
    const int col0 = blockIdx.x * 128;

    // A fill map: idx -> (row = idx>>2, k8 = (idx&3)*8), uint4 (8 bf16)
    const int a_row = tid >> 2;
    const int a_k8  = (tid & 3) << 3;
    // B fill map: n = tid&127, k8 = (tid>>7)*8 (+16 on second half)
    const int b_n  = tid & 127;
    const int b_k8 = (tid >> 7) << 3;

    float acc[2][8][4];
#pragma unroll
    for (int mt = 0; mt < 2; mt++)
#pragma unroll
        for (int nt = 0; nt < 8; nt++)
#pragma unroll
            for (int e = 0; e < 4; e++) acc[mt][nt][e] = 0.f;

    for (int k0 = 0; k0 < K; k0 += 32) {
        // ---- A tile: 128 x 32, 2 uint4 per thread
#pragma unroll
        for (int h = 0; h < 2; h++) {
            const int r  = a_row + h * 64;
            const uint4 v = *reinterpret_cast<const uint4*>(
                A + (size_t)(row0 + r) * K + k0 + a_k8);
            *reinterpret_cast<uint4*>(&As[r][a_k8]) = v;
        }
        // ---- B^T tile: Bs[n][k], coalesced global reads (lanes over n)
#pragma unroll
        for (int h = 0; h < 2; h++) {
            const int kb = b_k8 + h * 16;
#pragma unroll
            for (int kk = 0; kk < 8; kk++) {
                Bs[b_n][kb + kk] = W[(size_t)(k0 + kb + kk) * N + col0 + b_n];
            }
        }
        __syncthreads();

#pragma unroll
        for (int kk = 0; kk < 2; kk++) {
            const int kb = kk * 16;
            unsigned af[2][4];
#pragma unroll
            for (int mt = 0; mt < 2; mt++) {
                const int mr = wm * 32 + mt * 16;
                af[mt][0] = *reinterpret_cast<const unsigned*>(&As[mr + gid][kb + 2 * tig]);
                af[mt][1] = *reinterpret_cast<const unsigned*>(&As[mr + gid + 8][kb + 2 * tig]);
                af[mt][2] = *reinterpret_cast<const unsigned*>(&As[mr + gid][kb + 2 * tig + 8]);
                af[mt][3] = *reinterpret_cast<const unsigned*>(&As[mr + gid + 8][kb + 2 * tig + 8]);
            }
            unsigned bf[8][2];
#pragma unroll
            for (int nt = 0; nt < 8; nt++) {
                const int nc = wn * 64 + nt * 8 + gid;
                bf[nt][0] = *reinterpret_cast<const unsigned*>(&Bs[nc][kb + 2 * tig]);
                bf[nt][1] = *reinterpret_cast<const unsigned*>(&Bs[nc][kb + 2 * tig + 8]);
            }
#pragma unroll
            for (int mt = 0; mt < 2; mt++)
#pragma unroll
                for (int nt = 0; nt < 8; nt++)
                    mma16816(acc[mt][nt], af[mt], bf[nt]);
        }
        __syncthreads();
    }

    // ---- epilogue
#pragma unroll
    for (int mt = 0; mt < 2; mt++) {
#pragma unroll
        for (int nt = 0; nt < 8; nt++) {
            const int col = col0 + wn * 64 + nt * 8 + tig * 2;
            const float bx = bias[col], by = bias[col + 1];
            const int r0 = row0 + wm * 32 + mt * 16 + gid;
            const int r1 = r0 + 8;
            float v0 = acc[mt][nt][0] + bx;
            float v1 = acc[mt][nt][1] + by;
            float v2 = acc[mt][nt][2] + bx;
            float v3 = acc[mt][nt][3] + by;
            if (TANH) {
                v0 = tanhf(v0); v1 = tanhf(v1); v2 = tanhf(v2); v3 = tanhf(v3);
                __nv_bfloat162 p01 = __floats2bfloat162_rn(v0, v1);
                __nv_bfloat162 p23 = __floats2bfloat162_rn(v2, v3);
                *reinterpret_cast<__nv_bfloat162*>(Cb + (size_t)r0 * N + col) = p01;
                *reinterpret_cast<__nv_bfloat162*>(Cb + (size_t)r1 * N + col) = p23;
            } else {
                *reinterpret_cast<float2*>(Cf + (size_t)r0 * N + col) = make_float2(v0, v1);
                *reinterpret_cast<float2*>(Cf + (size_t)r1 * N + col) = make_float2(v2, v3);
            }
        }
    }
}

__global__ void __launch_bounds__(256)
gemm1_mma(const float* __restrict__ b1) {
    mma_gemm_body<HH, HH, 1>(g_Xb, g_W1b, b1, g_hb, nullptr);
}

__global__ void __launch_bounds__(256)
gemm2_mma(const float* __restrict__ b2) {
    mma_gemm_body<VV, HH, 0>(g_hb, g_W2b, b2, nullptr, g_logits);
}

// ---------------------------------------------------------------------------
// Warp-per-row logsumexp + gather of extended-label log-probs.
// 256 threads = 8 warps = 8 rows per block.
// ---------------------------------------------------------------------------
__global__ void __launch_bounds__(256)
lse_gather_kernel(const int* __restrict__ targets) {
    const int warp = threadIdx.x >> 5;
    const int lane = threadIdx.x & 31;
    const int row  = (blockIdx.x << 3) + warp;       // b*T + t
    const float* lr = g_logits + (size_t)row * VV;

    float4 v[8];
#pragma unroll
    for (int i = 0; i < 8; i++)
        v[i] = *reinterpret_cast<const float4*>(lr + (i * 128) + lane * 4);

    float m = -INFINITY;
#pragma unroll
    for (int i = 0; i < 8; i++) {
        m = fmaxf(m, fmaxf(fmaxf(v[i].x, v[i].y), fmaxf(v[i].z, v[i].w)));
    }
#pragma unroll
    for (int o = 16; o > 0; o >>= 1) m = fmaxf(m, __shfl_xor_sync(0xffffffffu, m, o));

    float s = 0.f;
#pragma unroll
    for (int i = 0; i < 8; i++) {
        s += __expf(v[i].x - m) + __expf(v[i].y - m) + __expf(v[i].z - m) + __expf(v[i].w - m);
    }
#pragma unroll
    for (int o = 16; o > 0; o >>= 1) s += __shfl_xor_sync(0xffffffffu, s, o);

    const float lse = m + __logf(s);

    const int b = row >> 10;                         // T = 1024
    const int* tg = targets + (b << 7);              // S = 128
    float* lpr = g_lp + (size_t)row * LL;
#pragma unroll
    for (int s0 = 0; s0 < 9; s0++) {
        const int st = s0 * 32 + lane;
        if (st < LL) {
            const int lab = (st & 1) ? tg[st >> 1] : 0;   // blank = PAD = 0
            lpr[st] = lr[lab] - lse;
        }
    }
}

// ---------------------------------------------------------------------------
// CTC forward scan: one WARP per batch element. 9 states per lane in regs,
// neighbor exchange via shfl_up, fused 3-way log-add, 2-deep lp prefetch.
// ---------------------------------------------------------------------------
__device__ __forceinline__ float logadd3(float a, float b, float c) {
    float m = fmaxf(fmaxf(a, b), c);
    float s = __expf(a - m) + __expf(b - m) + __expf(c - m);
    return m + __logf(s);
}

__global__ void __launch_bounds__(32)
ctc_warp_kernel(const int* __restrict__ targets, const int* __restrict__ input_lengths,
                float* __restrict__ out) {
    const int b    = blockIdx.x;
    const int lane = threadIdx.x;
    const int* tg  = targets + b * SS;
    const float* lpb = g_lp + (size_t)b * TT * LL;
    const int Tlen = input_lengths[b];

    // per-lane state indices: s = lane*9 + j, j in [0,9)
    bool act[9];
    bool sk[9];
#pragma unroll
    for (int j = 0; j < 9; j++) {
        const int s = lane * 9 + j;
        act[j] = (s < LL);
        sk[j] = false;
        if (act[j] && (s & 1) && s >= 3)
            sk[j] = (tg[s >> 1] != tg[(s >> 1) - 1]);
    }

    // init alpha(t=0)
    float r[9];
#pragma unroll
    for (int j = 0; j < 9; j++) {
        const int s = lane * 9 + j;
        r[j] = (s < 2) ? lpb[s] : NEGV;
    }

    // 2-deep prefetch of lp rows
    float cur[9], nx1[9];
#pragma unroll
    for (int j = 0; j < 9; j++) {
        const int s = lane * 9 + j;
        cur[j] = act[j] ? lpb[(size_t)LL + s] : 0.f;                       // t=1
        const int t2 = (2 < Tlen) ? 2 : (Tlen - 1);
        nx1[j] = act[j] ? lpb[(size_t)t2 * LL + s] : 0.f;                  // t=2
    }

    for (int t = 1; t < Tlen; ++t) {
        // prefetch t+2
        float nx2[9];
        {
            int tp = t + 2;
            if (tp >= Tlen) tp = Tlen - 1;
            const float* lprow = lpb + (size_t)tp * LL;
#pragma unroll
            for (int j = 0; j < 9; j++)
                nx2[j] = act[j] ? lprow[lane * 9 + j] : 0.f;
        }

        float up8 = __shfl_up_sync(0xffffffffu, r[8], 1);   // s-1 for j=0
        float up7 = __shfl_up_sync(0xffffffffu, r[7], 1);   // s-2 for j=0
        if (lane == 0) { up8 = NEGV; up7 = NEGV; }

        float nv[9];
#pragma unroll
        for (int j = 0; j < 9; j++) {
            const float pm1 = (j == 0) ? up8 : r[j - 1];
            const float pm2 = (j == 0) ? up7 : ((j == 1) ? up8 : r[j - 2]);
            const float c = sk[j] ? pm2 : NEGV;
            nv[j] = logadd3(r[j], pm1, c) + cur[j];
        }
#pragma unroll
        for (int j = 0; j < 9; j++) {
            r[j] = act[j] ? nv[j] : NEGV;
            cur[j] = nx1[j];
            nx1[j] = nx2[j];
        }
    }

    // target length
    int cnt = 0;
#pragma unroll
    for (int i = 0; i < 4; i++) cnt += (tg[lane + i * 32] != 0);
#pragma unroll
    for (int o = 16; o > 0; o >>= 1) cnt += __shfl_xor_sync(0xffffffffu, cnt, o);
    const int sb = cnt;

    __shared__ float fin[288];
#pragma unroll
    for (int j = 0; j < 9; j++) fin[lane * 9 + j] = r[j];
    __syncwarp();

    if (lane == 0) {
        const float e1 = fin[2 * sb - 1];
        const float e2 = fin[2 * sb];
        const float m = fmaxf(e1, e2);
        const float l = m + __logf(__expf(e1 - m) + __expf(e2 - m));
        out[b] = -l / (float)sb;
    }
}

// ---------------------------------------------------------------------------
extern "C" void kernel_launch(void* const* d_in, const int* in_sizes, int n_in,
                              void* d_out, int out_size) {
    const int*   targets = (const int*)  d_in[0];   // [32,128] int32
    const float* X       = (const float*)d_in[1];   // [32,1024,512]
    const int*   ilen    = (const int*)  d_in[2];   // [32]
    const float* W1      = (const float*)d_in[3];   // [512,512]
    const float* b1      = (const float*)d_in[4];   // [512]
    const float* W2      = (const float*)d_in[5];   // [512,1024]
    const float* b2      = (const float*)d_in[6];   // [1024]
    float*       out     = (float*)d_out;           // [32]

    const int M = BB * TT;  // 32768

    // bf16 conversions
    __nv_bfloat16* xb;  cudaGetSymbolAddress((void**)&xb,  g_Xb);
    __nv_bfloat16* w1b; cudaGetSymbolAddress((void**)&w1b, g_W1b);
    __nv_bfloat16* w2b; cudaGetSymbolAddress((void**)&w2b, g_W2b);

    f2bf_kernel<<<(M * HH) / (256 * 4), 256>>>(X, xb, M * HH);
    f2bf_kernel<<<(HH * HH) / (256 * 4), 256>>>(W1, w1b, HH * HH);
    f2bf_kernel<<<(HH * VV) / (256 * 4), 256>>>(W2, w2b, HH * VV);

    dim3 g1(HH / 128, M / 128);   // (4, 256)
    gemm1_mma<<<g1, 256>>>(b1);

    dim3 g2(VV / 128, M / 128);   // (8, 256)
    gemm2_mma<<<g2, 256>>>(b2);

    lse_gather_kernel<<<M / 8, 256>>>(targets);

    ctc_warp_kernel<<<BB, 32>>>(targets, ilen, out);
}

// round 3
// speedup vs baseline: 3.4892x; 2.1472x over previous
#include <cuda_runtime.h>
#include <cuda_bf16.h>
#include <math.h>

// Problem constants
#define BB 32
#define TT 1024
#define HH 512
#define VV 1024
#define SS 128
#define LL 257          // 2*S + 1
#define LPS 260         // padded row stride for p (16B-aligned rows)

// Scratch (device globals: allocation-free per harness rules)
__device__ __nv_bfloat16 g_Xb[(size_t)BB * TT * HH];   // 32 MB  : X in bf16
__device__ __nv_bfloat16 g_W1b[(size_t)HH * HH];       // 0.5 MB
__device__ __nv_bfloat16 g_W2b[(size_t)HH * VV];       // 1 MB
__device__ __nv_bfloat16 g_hb[(size_t)BB * TT * HH];   // 32 MB  : tanh(X@W1+b1) bf16
__device__ float g_logits[(size_t)BB * TT * VV];       // 128 MB : h@W2+b2
__device__ float g_p[(size_t)BB * TT * LPS + 64];      // 34 MB  : probs at ext labels

// ---------------------------------------------------------------------------
// float -> bf16 conversion (vectorized)
// ---------------------------------------------------------------------------
__global__ void __launch_bounds__(256)
f2bf_kernel(const float* __restrict__ in, __nv_bfloat16* __restrict__ out, int n) {
    int i = (blockIdx.x * 256 + threadIdx.x) * 4;
    if (i < n) {
        float4 v = *reinterpret_cast<const float4*>(in + i);
        __nv_bfloat162 p0 = __floats2bfloat162_rn(v.x, v.y);
        __nv_bfloat162 p1 = __floats2bfloat162_rn(v.z, v.w);
        *reinterpret_cast<__nv_bfloat162*>(out + i)     = p0;
        *reinterpret_cast<__nv_bfloat162*>(out + i + 2) = p1;
    }
}

// ---------------------------------------------------------------------------
// bf16 tensor-core GEMM: C[M,N] = act(A[M,K] @ W[K,N] + bias)
// 128x128 block tile, BK=32, 256 threads (8 warps, 4x2), warp tile 32x64,
// mma.sync.m16n8k16 bf16 -> f32 accum.
// ---------------------------------------------------------------------------
__device__ __forceinline__ void mma16816(float* c, const unsigned* a, const unsigned* b) {
    asm volatile(
        "mma.sync.aligned.m16n8k16.row.col.f32.bf16.bf16.f32 "
        "{%0,%1,%2,%3}, {%4,%5,%6,%7}, {%8,%9}, {%0,%1,%2,%3};"
        : "+f"(c[0]), "+f"(c[1]), "+f"(c[2]), "+f"(c[3])
        : "r"(a[0]), "r"(a[1]), "r"(a[2]), "r"(a[3]), "r"(b[0]), "r"(b[1]));
}

#define ASTRIDE 40   // halves; conflict-free A-frag LDS
#define BSTRIDE 38   // halves; near-conflict-free B-frag LDS

template <int N, int K, int TANH>
__device__ __forceinline__ void mma_gemm_body(const __nv_bfloat16* __restrict__ A,
                                              const __nv_bfloat16* __restrict__ W,
                                              const float* __restrict__ bias,
                                              __nv_bfloat16* __restrict__ Cb,
                                              float* __restrict__ Cf) {
    __shared__ __nv_bfloat16 As[128][ASTRIDE];
    __shared__ __nv_bfloat16 Bs[128][BSTRIDE];   // B^T tile: Bs[n][k]

    const int tid  = threadIdx.x;
    const int lane = tid & 31;
    const int warp = tid >> 5;
    const int wm   = warp & 3;
    const int wn   = warp >> 2;
    const int gid  = lane >> 2;
    const int tig  = lane & 3;

    const int row0 = blockIdx.y * 128;
    const int col0 = blockIdx.x * 128;

    const int a_row = tid >> 2;
    const int a_k8  = (tid & 3) << 3;
    const int b_n  = tid & 127;
    const int b_k8 = (tid >> 7) << 3;

    float acc[2][8][4];
#pragma unroll
    for (int mt = 0; mt < 2; mt++)
#pragma unroll
        for (int nt = 0; nt < 8; nt++)
#pragma unroll
            for (int e = 0; e < 4; e++) acc[mt][nt][e] = 0.f;

    for (int k0 = 0; k0 < K; k0 += 32) {
#pragma unroll
        for (int h = 0; h < 2; h++) {
            const int r  = a_row + h * 64;
            const uint4 v = *reinterpret_cast<const uint4*>(
                A + (size_t)(row0 + r) * K + k0 + a_k8);
            *reinterpret_cast<uint4*>(&As[r][a_k8]) = v;
        }
#pragma unroll
        for (int h = 0; h < 2; h++) {
            const int kb = b_k8 + h * 16;
#pragma unroll
            for (int kk = 0; kk < 8; kk++) {
                Bs[b_n][kb + kk] = W[(size_t)(k0 + kb + kk) * N + col0 + b_n];
            }
        }
        __syncthreads();

#pragma unroll
        for (int kk = 0; kk < 2; kk++) {
            const int kb = kk * 16;
            unsigned af[2][4];
#pragma unroll
            for (int mt = 0; mt < 2; mt++) {
                const int mr = wm * 32 + mt * 16;
                af[mt][0] = *reinterpret_cast<const unsigned*>(&As[mr + gid][kb + 2 * tig]);
                af[mt][1] = *reinterpret_cast<const unsigned*>(&As[mr + gid + 8][kb + 2 * tig]);
                af[mt][2] = *reinterpret_cast<const unsigned*>(&As[mr + gid][kb + 2 * tig + 8]);
                af[mt][3] = *reinterpret_cast<const unsigned*>(&As[mr + gid + 8][kb + 2 * tig + 8]);
            }
            unsigned bf[8][2];
#pragma unroll
            for (int nt = 0; nt < 8; nt++) {
                const int nc = wn * 64 + nt * 8 + gid;
                bf[nt][0] = *reinterpret_cast<const unsigned*>(&Bs[nc][kb + 2 * tig]);
                bf[nt][1] = *reinterpret_cast<const unsigned*>(&Bs[nc][kb + 2 * tig + 8]);
            }
#pragma unroll
            for (int mt = 0; mt < 2; mt++)
#pragma unroll
                for (int nt = 0; nt < 8; nt++)
                    mma16816(acc[mt][nt], af[mt], bf[nt]);
        }
        __syncthreads();
    }

#pragma unroll
    for (int mt = 0; mt < 2; mt++) {
#pragma unroll
        for (int nt = 0; nt < 8; nt++) {
            const int col = col0 + wn * 64 + nt * 8 + tig * 2;
            const float bx = bias[col], by = bias[col + 1];
            const int r0 = row0 + wm * 32 + mt * 16 + gid;
            const int r1 = r0 + 8;
            float v0 = acc[mt][nt][0] + bx;
            float v1 = acc[mt][nt][1] + by;
            float v2 = acc[mt][nt][2] + bx;
            float v3 = acc[mt][nt][3] + by;
            if (TANH) {
                v0 = tanhf(v0); v1 = tanhf(v1); v2 = tanhf(v2); v3 = tanhf(v3);
                __nv_bfloat162 p01 = __floats2bfloat162_rn(v0, v1);
                __nv_bfloat162 p23 = __floats2bfloat162_rn(v2, v3);
                *reinterpret_cast<__nv_bfloat162*>(Cb + (size_t)r0 * N + col) = p01;
                *reinterpret_cast<__nv_bfloat162*>(Cb + (size_t)r1 * N + col) = p23;
            } else {
                *reinterpret_cast<float2*>(Cf + (size_t)r0 * N + col) = make_float2(v0, v1);
                *reinterpret_cast<float2*>(Cf + (size_t)r1 * N + col) = make_float2(v2, v3);
            }
        }
    }
}

__global__ void __launch_bounds__(256)
gemm1_mma(const float* __restrict__ b1) {
    mma_gemm_body<HH, HH, 1>(g_Xb, g_W1b, b1, g_hb, nullptr);
}

__global__ void __launch_bounds__(256)
gemm2_mma(const float* __restrict__ b2) {
    mma_gemm_body<VV, HH, 0>(g_hb, g_W2b, b2, nullptr, g_logits);
}

// ---------------------------------------------------------------------------
// Warp-per-row logsumexp + gather: writes PROBABILITIES p = exp(logit - lse)
// at the 257 extended-label positions (row stride LPS=260).
// ---------------------------------------------------------------------------
__global__ void __launch_bounds__(256)
lse_gather_kernel(const int* __restrict__ targets) {
    const int warp = threadIdx.x >> 5;
    const int lane = threadIdx.x & 31;
    const int row  = (blockIdx.x << 3) + warp;       // b*T + t
    const float* lr = g_logits + (size_t)row * VV;

    float4 v[8];
#pragma unroll
    for (int i = 0; i < 8; i++)
        v[i] = *reinterpret_cast<const float4*>(lr + (i * 128) + lane * 4);

    float m = -INFINITY;
#pragma unroll
    for (int i = 0; i < 8; i++)
        m = fmaxf(m, fmaxf(fmaxf(v[i].x, v[i].y), fmaxf(v[i].z, v[i].w)));
#pragma unroll
    for (int o = 16; o > 0; o >>= 1) m = fmaxf(m, __shfl_xor_sync(0xffffffffu, m, o));

    float s = 0.f;
#pragma unroll
    for (int i = 0; i < 8; i++)
        s += __expf(v[i].x - m) + __expf(v[i].y - m) + __expf(v[i].z - m) + __expf(v[i].w - m);
#pragma unroll
    for (int o = 16; o > 0; o >>= 1) s += __shfl_xor_sync(0xffffffffu, s, o);

    const float lse = m + __logf(s);

    const int b = row >> 10;                         // T = 1024
    const int* tg = targets + (b << 7);              // S = 128
    float* pr = g_p + (size_t)row * LPS;
#pragma unroll
    for (int s0 = 0; s0 < 9; s0++) {
        const int st = s0 * 32 + lane;
        if (st < LL) {
            const int lab = (st & 1) ? tg[st >> 1] : 0;   // blank = PAD = 0
            pr[st] = __expf(lr[lab] - lse);
        }
    }
}

// ---------------------------------------------------------------------------
// Linear-domain CTC forward scan: one WARP per batch element.
// 8 contiguous states per lane (+ state 256 on lane 31), renorm every 8 steps.
// alpha'[s] = (alpha[s] + alpha[s-1] + skip[s]*alpha[s-2]) * p[t][s]
// ---------------------------------------------------------------------------
__global__ void __launch_bounds__(32)
ctc_lin_kernel(const int* __restrict__ targets, const int* __restrict__ input_lengths,
               float* __restrict__ out) {
    const int b    = blockIdx.x;
    const int lane = threadIdx.x;
    const int* tg  = targets + b * SS;
    const float* base = g_p + (size_t)b * TT * LPS;
    const int Tlen = input_lengths[b];

    // skip coefficients (1.0 where the s-2 transition is allowed)
    float cm[9];
#pragma unroll
    for (int j = 0; j < 9; j++) {
        const int s = lane * 8 + j;            // j==8 real only on lane 31 (s=256, even)
        float c = 0.f;
        if (j < 8 && (s & 1) && s >= 3 && s < LL)
            c = (tg[s >> 1] != tg[(s >> 1) - 1]) ? 1.f : 0.f;
        cm[j] = c;
    }

    // init alpha(t=0), pre-scaled by 2^100
    const float init_sc = __int_as_float((100 + 127) << 23);
    float r[9];
#pragma unroll
    for (int j = 0; j < 9; j++) {
        const int s = lane * 8 + j;
        r[j] = (s < 2) ? base[s] * init_sc : 0.f;
    }
    int Esum = 100;

    // 4-slot register ring of p rows (each slot: float4 x2 + 1 scalar)
    float4 A0, B0, A1, B1, A2, B2, A3, B3;
    float  C0, C1, C2, C3;

#define LOADSLOT(Af, Bf, Cf, tp_) do {                                        \
        int tp = (tp_); if (tp > Tlen - 1) tp = Tlen - 1;                     \
        const float* rp = base + (size_t)tp * LPS + lane * 8;                 \
        Af = *reinterpret_cast<const float4*>(rp);                            \
        Bf = *reinterpret_cast<const float4*>(rp + 4);                        \
        Cf = rp[8];                                                           \
    } while (0)

#define STEP(Af, Bf, Cf) do {                                                 \
        float u1 = __shfl_up_sync(0xffffffffu, r[7], 1);                      \
        float u2 = __shfl_up_sync(0xffffffffu, r[6], 1);                      \
        if (lane == 0) { u1 = 0.f; u2 = 0.f; }                                \
        float n0 = fmaf(cm[0], u2,   r[0] + u1)   * Af.x;                     \
        float n1 = fmaf(cm[1], u1,   r[1] + r[0]) * Af.y;                     \
        float n2 = fmaf(cm[2], r[0], r[2] + r[1]) * Af.z;                     \
        float n3 = fmaf(cm[3], r[1], r[3] + r[2]) * Af.w;                     \
        float n4 = fmaf(cm[4], r[2], r[4] + r[3]) * Bf.x;                     \
        float n5 = fmaf(cm[5], r[3], r[5] + r[4]) * Bf.y;                     \
        float n6 = fmaf(cm[6], r[4], r[6] + r[5]) * Bf.z;                     \
        float n7 = fmaf(cm[7], r[5], r[7] + r[6]) * Bf.w;                     \
        float n8 = fmaf(cm[8], r[6], r[8] + r[7]) * Cf;                       \
        r[0]=n0; r[1]=n1; r[2]=n2; r[3]=n3; r[4]=n4;                          \
        r[5]=n5; r[6]=n6; r[7]=n7; r[8]=n8;                                   \
    } while (0)

#define RENORM() do {                                                         \
        float m = r[0];                                                       \
        m = fmaxf(m, r[1]); m = fmaxf(m, r[2]); m = fmaxf(m, r[3]);           \
        m = fmaxf(m, r[4]); m = fmaxf(m, r[5]); m = fmaxf(m, r[6]);           \
        m = fmaxf(m, r[7]); m = fmaxf(m, r[8]);                               \
        m = fmaxf(m, __shfl_xor_sync(0xffffffffu, m, 16));                    \
        m = fmaxf(m, __shfl_xor_sync(0xffffffffu, m, 8));                     \
        m = fmaxf(m, __shfl_xor_sync(0xffffffffu, m, 4));                     \
        m = fmaxf(m, __shfl_xor_sync(0xffffffffu, m, 2));                     \
        m = fmaxf(m, __shfl_xor_sync(0xffffffffu, m, 1));                     \
        int ex = (__float_as_int(m) >> 23) & 255;                             \
        int se = 60 - (ex - 127);                                             \
        se = (se > 127) ? 127 : ((se < -126) ? -126 : se);                    \
        const float sc = __int_as_float((se + 127) << 23);                    \
        r[0]*=sc; r[1]*=sc; r[2]*=sc; r[3]*=sc; r[4]*=sc;                     \
        r[5]*=sc; r[6]*=sc; r[7]*=sc; r[8]*=sc;                               \
        Esum += se;                                                           \
    } while (0)

    int t = 1;
    LOADSLOT(A0, B0, C0, 1);
    LOADSLOT(A1, B1, C1, 2);
    LOADSLOT(A2, B2, C2, 3);
    LOADSLOT(A3, B3, C3, 4);

    if (Tlen > 1) {
        for (;;) {
            STEP(A0, B0, C0); LOADSLOT(A0, B0, C0, t + 4);
            if (++t >= Tlen) break;
            if ((t & 7) == 0) RENORM();
            STEP(A1, B1, C1); LOADSLOT(A1, B1, C1, t + 4);
            if (++t >= Tlen) break;
            if ((t & 7) == 0) RENORM();
            STEP(A2, B2, C2); LOADSLOT(A2, B2, C2, t + 4);
            if (++t >= Tlen) break;
            if ((t & 7) == 0) RENORM();
            STEP(A3, B3, C3); LOADSLOT(A3, B3, C3, t + 4);
            if (++t >= Tlen) break;
            if ((t & 7) == 0) RENORM();
        }
    }

    // final readout
    __shared__ float fin[LPS];
#pragma unroll
    for (int j = 0; j < 8; j++) fin[lane * 8 + j] = r[j];
    if (lane == 31) fin[256] = r[8];
    __syncwarp();

    int cnt = 0;
#pragma unroll
    for (int i = 0; i < 4; i++) cnt += (tg[lane + i * 32] != 0);
#pragma unroll
    for (int o = 16; o > 0; o >>= 1) cnt += __shfl_xor_sync(0xffffffffu, cnt, o);
    const int sb = cnt;

    if (lane == 0) {
        const float e = fin[2 * sb - 1] + fin[2 * sb];
        out[b] = ((float)Esum * 0.6931471805599453f - logf(e)) / (float)sb;
    }
}

// ---------------------------------------------------------------------------
extern "C" void kernel_launch(void* const* d_in, const int* in_sizes, int n_in,
                              void* d_out, int out_size) {
    const int*   targets = (const int*)  d_in[0];   // [32,128] int32
    const float* X       = (const float*)d_in[1];   // [32,1024,512]
    const int*   ilen    = (const int*)  d_in[2];   // [32]
    const float* W1      = (const float*)d_in[3];   // [512,512]
    const float* b1      = (const float*)d_in[4];   // [512]
    const float* W2      = (const float*)d_in[5];   // [512,1024]
    const float* b2      = (const float*)d_in[6];   // [1024]
    float*       out     = (float*)d_out;           // [32]

    const int M = BB * TT;  // 32768

    __nv_bfloat16* xb;  cudaGetSymbolAddress((void**)&xb,  g_Xb);
    __nv_bfloat16* w1b; cudaGetSymbolAddress((void**)&w1b, g_W1b);
    __nv_bfloat16* w2b; cudaGetSymbolAddress((void**)&w2b, g_W2b);

    f2bf_kernel<<<(M * HH) / (256 * 4), 256>>>(X, xb, M * HH);
    f2bf_kernel<<<(HH * HH) / (256 * 4), 256>>>(W1, w1b, HH * HH);
    f2bf_kernel<<<(HH * VV) / (256 * 4), 256>>>(W2, w2b, HH * VV);

    dim3 g1(HH / 128, M / 128);   // (4, 256)
    gemm1_mma<<<g1, 256>>>(b1);

    dim3 g2(VV / 128, M / 128);   // (8, 256)
    gemm2_mma<<<g2, 256>>>(b2);

    lse_gather_kernel<<<M / 8, 256>>>(targets);

    ctc_lin_kernel<<<BB, 32>>>(targets, ilen, out);
}

// round 5
// speedup vs baseline: 3.7687x; 1.0801x over previous
#include <cuda_runtime.h>
#include <cuda_bf16.h>
#include <math.h>
#include <stdint.h>

// Problem constants
#define BB 32
#define TT 1024
#define HH 512
#define VV 1024
#define SS 128
#define LL 257          // 2*S + 1
#define LPS 260         // padded row stride for p

// GEMM tile config
#define BK 64
#define ASTR 72                      // halves per padded tile row (144 B, 16B-aligned)
#define TILE_H (128 * ASTR)          // halves per tile (9216)
#define GSM (2 * 2 * TILE_H * 2)     // dynamic smem bytes: 2 stages x (A,B) = 73728

// Scratch (device globals: allocation-free per harness rules)
__device__ __nv_bfloat16 g_Xb[(size_t)BB * TT * HH];   // 32 MB : X bf16 (K-major)
__device__ __nv_bfloat16 g_W1t[(size_t)HH * HH];       // W1^T bf16 [N=512][K=512]
__device__ __nv_bfloat16 g_W2t[(size_t)VV * HH];       // W2^T bf16 [N=1024][K=512]
__device__ __nv_bfloat16 g_hb[(size_t)BB * TT * HH];   // 32 MB : tanh(X@W1+b1) bf16
__device__ float g_logits[(size_t)BB * TT * VV];       // 128 MB: h@W2+b2
__device__ float g_p[(size_t)BB * TT * LPS + 64];      // 34 MB : probs at ext labels

// ---------------------------------------------------------------------------
// PTX helpers
// ---------------------------------------------------------------------------
__device__ __forceinline__ unsigned su32(const void* p) {
    unsigned a;
    asm("{ .reg .u64 t; cvta.to.shared.u64 t, %1; cvt.u32.u64 %0, t; }" : "=r"(a) : "l"(p));
    return a;
}
__device__ __forceinline__ void cp16(unsigned dst, const void* src) {
    asm volatile("cp.async.cg.shared.global [%0], [%1], 16;" :: "r"(dst), "l"(src));
}
__device__ __forceinline__ void cp_commit() { asm volatile("cp.async.commit_group;" ::: "memory"); }
__device__ __forceinline__ void cp_wait1()  { asm volatile("cp.async.wait_group 1;" ::: "memory"); }
__device__ __forceinline__ void cp_wait0()  { asm volatile("cp.async.wait_group 0;" ::: "memory"); }

__device__ __forceinline__ void mma16816(float* c, const unsigned* a, const unsigned* b) {
    asm volatile(
        "mma.sync.aligned.m16n8k16.row.col.f32.bf16.bf16.f32 "
        "{%0,%1,%2,%3}, {%4,%5,%6,%7}, {%8,%9}, {%0,%1,%2,%3};"
        : "+f"(c[0]), "+f"(c[1]), "+f"(c[2]), "+f"(c[3])
        : "r"(a[0]), "r"(a[1]), "r"(a[2]), "r"(a[3]), "r"(b[0]), "r"(b[1]));
}

// ---------------------------------------------------------------------------
// Conversion kernels
// ---------------------------------------------------------------------------
__global__ void __launch_bounds__(256)
f2bf_kernel(const float* __restrict__ in, __nv_bfloat16* __restrict__ out, int n) {
    int i = (blockIdx.x * 256 + threadIdx.x) * 4;
    if (i < n) {
        float4 v = *reinterpret_cast<const float4*>(in + i);
        *reinterpret_cast<__nv_bfloat162*>(out + i)     = __floats2bfloat162_rn(v.x, v.y);
        *reinterpret_cast<__nv_bfloat162*>(out + i + 2) = __floats2bfloat162_rn(v.z, v.w);
    }
}

// transpose + convert: in [K][N] fp32 row-major -> out [N][K] bf16 row-major
__global__ void __launch_bounds__(256)
f2bfT_kernel(const float* __restrict__ in, __nv_bfloat16* __restrict__ out, int K, int N) {
    __shared__ float tile[32][33];
    const int n0 = blockIdx.x * 32, k0 = blockIdx.y * 32;
    const int tx = threadIdx.x & 31, ty = threadIdx.x >> 5;   // (32,8)
#pragma unroll
    for (int i = 0; i < 32; i += 8)
        tile[ty + i][tx] = in[(size_t)(k0 + ty + i) * N + n0 + tx];
    __syncthreads();
#pragma unroll
    for (int i = 0; i < 32; i += 8)
        out[(size_t)(n0 + ty + i) * K + k0 + tx] = __float2bfloat16(tile[tx][ty + i]);
}

// ---------------------------------------------------------------------------
// Pipelined bf16 mma.sync GEMM: C[M,N] = act(A[M,512] @ BT[N,512]^T + bias)
// 128x128 block tile, BK=64, cp.async 2-stage double buffer, 8 warps (4x2),
// warp tile 32x64, m16n8k16 HMMA with f32 accumulators.
// ---------------------------------------------------------------------------
template <int N, int TANH>
__global__ void __launch_bounds__(256)
gemm_cp(const __nv_bfloat16* __restrict__ A, const __nv_bfloat16* __restrict__ BT,
        const float* __restrict__ bias, __nv_bfloat16* __restrict__ Cb,
        float* __restrict__ Cf) {
    extern __shared__ __align__(16) __nv_bfloat16 sm[];   // [2 stages][A,B][128][ASTR]
    const unsigned sbase = su32(sm);

    const int tid  = threadIdx.x;
    const int lane = tid & 31;
    const int warp = tid >> 5;
    const int wm   = warp & 3;          // m offset wm*32
    const int wn   = warp >> 2;         // n offset wn*64
    const int gid  = lane >> 2;
    const int tig  = lane & 3;

    const int row0 = blockIdx.y * 128;
    const int col0 = blockIdx.x * 128;

    // cp.async fill map: thread -> tile row (tid>>1), 4 granules of 16B (8 halves)
    const int frow = tid >> 1;
    const int fg0  = (tid & 1) * 4;
    const __nv_bfloat16* Ap = A  + (size_t)(row0 + frow) * HH;
    const __nv_bfloat16* Bp = BT + (size_t)(col0 + frow) * HH;

    auto issue = [&](int c) {
        const unsigned buf = (unsigned)(c & 1);
        const unsigned abase = sbase + buf * (2u * TILE_H * 2u);
        const unsigned bbase = abase + TILE_H * 2u;
        const unsigned rowoff = (unsigned)(frow * ASTR * 2);
        const int k0 = c * BK;
#pragma unroll
        for (int g = 0; g < 4; g++) {
            const int kk = (fg0 + g) * 8;
            cp16(abase + rowoff + (unsigned)(fg0 + g) * 16u, Ap + k0 + kk);
            cp16(bbase + rowoff + (unsigned)(fg0 + g) * 16u, Bp + k0 + kk);
        }
        cp_commit();
    };

    float acc[2][8][4];
#pragma unroll
    for (int mt = 0; mt < 2; mt++)
#pragma unroll
        for (int nt = 0; nt < 8; nt++)
#pragma unroll
            for (int e = 0; e < 4; e++) acc[mt][nt][e] = 0.f;

    issue(0);
    issue(1);

    const int NC = HH / BK;   // 8 chunks
#pragma unroll 1
    for (int c = 0; c < NC; ++c) {
        if (c < NC - 2) cp_wait1(); else cp_wait0();
        __syncthreads();

        const __nv_bfloat16* As = sm + (size_t)(c & 1) * 2 * TILE_H;
        const __nv_bfloat16* Bs = As + TILE_H;

#pragma unroll
        for (int kk = 0; kk < BK / 16; kk++) {
            const int kb = kk * 16;
            unsigned af[2][4];
#pragma unroll
            for (int mt = 0; mt < 2; mt++) {
                const int mr = wm * 32 + mt * 16;
                af[mt][0] = *reinterpret_cast<const unsigned*>(&As[(mr + gid) * ASTR + kb + 2 * tig]);
                af[mt][1] = *reinterpret_cast<const unsigned*>(&As[(mr + gid + 8) * ASTR + kb + 2 * tig]);
                af[mt][2] = *reinterpret_cast<const unsigned*>(&As[(mr + gid) * ASTR + kb + 2 * tig + 8]);
                af[mt][3] = *reinterpret_cast<const unsigned*>(&As[(mr + gid + 8) * ASTR + kb + 2 * tig + 8]);
            }
            unsigned bf[8][2];
#pragma unroll
            for (int nt = 0; nt < 8; nt++) {
                const int nc = wn * 64 + nt * 8 + gid;
                bf[nt][0] = *reinterpret_cast<const unsigned*>(&Bs[nc * ASTR + kb + 2 * tig]);
                bf[nt][1] = *reinterpret_cast<const unsigned*>(&Bs[nc * ASTR + kb + 2 * tig + 8]);
            }
#pragma unroll
            for (int mt = 0; mt < 2; mt++)
#pragma unroll
                for (int nt = 0; nt < 8; nt++)
                    mma16816(acc[mt][nt], af[mt], bf[nt]);
        }
        __syncthreads();
        if (c + 2 < NC) issue(c + 2);
    }

    // epilogue
#pragma unroll
    for (int mt = 0; mt < 2; mt++) {
#pragma unroll
        for (int nt = 0; nt < 8; nt++) {
            const int col = col0 + wn * 64 + nt * 8 + tig * 2;
            const float bx = bias[col], by = bias[col + 1];
            const int r0 = row0 + wm * 32 + mt * 16 + gid;
            const int r1 = r0 + 8;
            float v0 = acc[mt][nt][0] + bx;
            float v1 = acc[mt][nt][1] + by;
            float v2 = acc[mt][nt][2] + bx;
            float v3 = acc[mt][nt][3] + by;
            if (TANH) {
                __nv_bfloat162 p01 = __floats2bfloat162_rn(tanhf(v0), tanhf(v1));
                __nv_bfloat162 p23 = __floats2bfloat162_rn(tanhf(v2), tanhf(v3));
                *reinterpret_cast<__nv_bfloat162*>(Cb + (size_t)r0 * N + col) = p01;
                *reinterpret_cast<__nv_bfloat162*>(Cb + (size_t)r1 * N + col) = p23;
            } else {
                *reinterpret_cast<float2*>(Cf + (size_t)r0 * N + col) = make_float2(v0, v1);
                *reinterpret_cast<float2*>(Cf + (size_t)r1 * N + col) = make_float2(v2, v3);
            }
        }
    }
}

// ---------------------------------------------------------------------------
// Warp-per-row logsumexp + gather: writes probabilities p = exp(logit - lse).
// Gathered values use accurate expf (they get multiplied 1024x in the scan).
// ---------------------------------------------------------------------------
__global__ void __launch_bounds__(256)
lse_gather_kernel(const int* __restrict__ targets) {
    const int warp = threadIdx.x >> 5;
    const int lane = threadIdx.x & 31;
    const int row  = (blockIdx.x << 3) + warp;       // b*T + t
    const float* lr = g_logits + (size_t)row * VV;

    float4 v[8];
#pragma unroll
    for (int i = 0; i < 8; i++)
        v[i] = *reinterpret_cast<const float4*>(lr + (i * 128) + lane * 4);

    float m = -INFINITY;
#pragma unroll
    for (int i = 0; i < 8; i++)
        m = fmaxf(m, fmaxf(fmaxf(v[i].x, v[i].y), fmaxf(v[i].z, v[i].w)));
#pragma unroll
    for (int o = 16; o > 0; o >>= 1) m = fmaxf(m, __shfl_xor_sync(0xffffffffu, m, o));

    float s = 0.f;
#pragma unroll
    for (int i = 0; i < 8; i++)
        s += __expf(v[i].x - m) + __expf(v[i].y - m) + __expf(v[i].z - m) + __expf(v[i].w - m);
#pragma unroll
    for (int o = 16; o > 0; o >>= 1) s += __shfl_xor_sync(0xffffffffu, s, o);

    const float lse = m + logf(s);

    const int b = row >> 10;                         // T = 1024
    const int* tg = targets + (b << 7);              // S = 128
    float* pr = g_p + (size_t)row * LPS;
#pragma unroll
    for (int s0 = 0; s0 < 9; s0++) {
        const int st = s0 * 32 + lane;
        if (st < LL) {
            const int lab = (st & 1) ? tg[st >> 1] : 0;   // blank = PAD = 0
            pr[st] = expf(lr[lab] - lse);                 // accurate exp
        }
    }
}

// ---------------------------------------------------------------------------
// Linear-domain CTC forward scan: one WARP per batch element.
// 8 contiguous states per lane (+ state 256 on lane 31), renorm every 8 steps.
// ---------------------------------------------------------------------------
__global__ void __launch_bounds__(32)
ctc_lin_kernel(const int* __restrict__ targets, const int* __restrict__ input_lengths,
               float* __restrict__ out) {
    const int b    = blockIdx.x;
    const int lane = threadIdx.x;
    const int* tg  = targets + b * SS;
    const float* base = g_p + (size_t)b * TT * LPS;
    const int Tlen = input_lengths[b];

    float cm[9];
#pragma unroll
    for (int j = 0; j < 9; j++) {
        const int s = lane * 8 + j;
        float c = 0.f;
        if (j < 8 && (s & 1) && s >= 3 && s < LL)
            c = (tg[s >> 1] != tg[(s >> 1) - 1]) ? 1.f : 0.f;
        cm[j] = c;
    }

    const float init_sc = __int_as_float((100 + 127) << 23);
    float r[9];
#pragma unroll
    for (int j = 0; j < 9; j++) {
        const int s = lane * 8 + j;
        r[j] = (s < 2) ? base[s] * init_sc : 0.f;
    }
    int Esum = 100;

    float4 A0, B0, A1, B1, A2, B2, A3, B3;
    float  C0, C1, C2, C3;

#define LOADSLOT(Af, Bf, Cf, tp_) do {                                        \
        int tp = (tp_); if (tp > Tlen - 1) tp = Tlen - 1;                     \
        const float* rp = base + (size_t)tp * LPS + lane * 8;                 \
        Af = *reinterpret_cast<const float4*>(rp);                            \
        Bf = *reinterpret_cast<const float4*>(rp + 4);                        \
        Cf = rp[8];                                                           \
    } while (0)

#define STEP(Af, Bf, Cf) do {                                                 \
        float u1 = __shfl_up_sync(0xffffffffu, r[7], 1);                      \
        float u2 = __shfl_up_sync(0xffffffffu, r[6], 1);                      \
        if (lane == 0) { u1 = 0.f; u2 = 0.f; }                                \
        float n0 = fmaf(cm[0], u2,   r[0] + u1)   * Af.x;                     \
        float n1 = fmaf(cm[1], u1,   r[1] + r[0]) * Af.y;                     \
        float n2 = fmaf(cm[2], r[0], r[2] + r[1]) * Af.z;                     \
        float n3 = fmaf(cm[3], r[1], r[3] + r[2]) * Af.w;                     \
        float n4 = fmaf(cm[4], r[2], r[4] + r[3]) * Bf.x;                     \
        float n5 = fmaf(cm[5], r[3], r[5] + r[4]) * Bf.y;                     \
        float n6 = fmaf(cm[6], r[4], r[6] + r[5]) * Bf.z;                     \
        float n7 = fmaf(cm[7], r[5], r[7] + r[6]) * Bf.w;                     \
        float n8 = fmaf(cm[8], r[6], r[8] + r[7]) * Cf;                       \
        r[0]=n0; r[1]=n1; r[2]=n2; r[3]=n3; r[4]=n4;                          \
        r[5]=n5; r[6]=n6; r[7]=n7; r[8]=n8;                                   \
    } while (0)

#define RENORM() do {                                                         \
        float m = r[0];                                                       \
        m = fmaxf(m, r[1]); m = fmaxf(m, r[2]); m = fmaxf(m, r[3]);           \
        m = fmaxf(m, r[4]); m = fmaxf(m, r[5]); m = fmaxf(m, r[6]);           \
        m = fmaxf(m, r[7]); m = fmaxf(m, r[8]);                               \
        m = fmaxf(m, __shfl_xor_sync(0xffffffffu, m, 16));                    \
        m = fmaxf(m, __shfl_xor_sync(0xffffffffu, m, 8));                     \
        m = fmaxf(m, __shfl_xor_sync(0xffffffffu, m, 4));                     \
        m = fmaxf(m, __shfl_xor_sync(0xffffffffu, m, 2));                     \
        m = fmaxf(m, __shfl_xor_sync(0xffffffffu, m, 1));                     \
        int ex = (__float_as_int(m) >> 23) & 255;                             \
        int se = 60 - (ex - 127);                                             \
        se = (se > 127) ? 127 : ((se < -126) ? -126 : se);                    \
        const float sc = __int_as_float((se + 127) << 23);                    \
        r[0]*=sc; r[1]*=sc; r[2]*=sc; r[3]*=sc; r[4]*=sc;                     \
        r[5]*=sc; r[6]*=sc; r[7]*=sc; r[8]*=sc;                               \
        Esum += se;                                                           \
    } while (0)

    int t = 1;
    LOADSLOT(A0, B0, C0, 1);
    LOADSLOT(A1, B1, C1, 2);
    LOADSLOT(A2, B2, C2, 3);
    LOADSLOT(A3, B3, C3, 4);

    if (Tlen > 1) {
        for (;;) {
            STEP(A0, B0, C0); LOADSLOT(A0, B0, C0, t + 4);
            if (++t >= Tlen) break;
            if ((t & 7) == 0) RENORM();
            STEP(A1, B1, C1); LOADSLOT(A1, B1, C1, t + 4);
            if (++t >= Tlen) break;
            if ((t & 7) == 0) RENORM();
            STEP(A2, B2, C2); LOADSLOT(A2, B2, C2, t + 4);
            if (++t >= Tlen) break;
            if ((t & 7) == 0) RENORM();
            STEP(A3, B3, C3); LOADSLOT(A3, B3, C3, t + 4);
            if (++t >= Tlen) break;
            if ((t & 7) == 0) RENORM();
        }
    }

    __shared__ float fin[LPS];
#pragma unroll
    for (int j = 0; j < 8; j++) fin[lane * 8 + j] = r[j];
    if (lane == 31) fin[256] = r[8];
    __syncwarp();

    int cnt = 0;
#pragma unroll
    for (int i = 0; i < 4; i++) cnt += (tg[lane + i * 32] != 0);
#pragma unroll
    for (int o = 16; o > 0; o >>= 1) cnt += __shfl_xor_sync(0xffffffffu, cnt, o);
    const int sb = cnt;

    if (lane == 0) {
        const float e = fin[2 * sb - 1] + fin[2 * sb];
        out[b] = ((float)Esum * 0.6931471805599453f - logf(e)) / (float)sb;
    }
}

// ---------------------------------------------------------------------------
extern "C" void kernel_launch(void* const* d_in, const int* in_sizes, int n_in,
                              void* d_out, int out_size) {
    const int*   targets = (const int*)  d_in[0];   // [32,128] int32
    const float* X       = (const float*)d_in[1];   // [32,1024,512]
    const int*   ilen    = (const int*)  d_in[2];   // [32]
    const float* W1      = (const float*)d_in[3];   // [512,512]
    const float* b1      = (const float*)d_in[4];   // [512]
    const float* W2      = (const float*)d_in[5];   // [512,1024]
    const float* b2      = (const float*)d_in[6];   // [1024]
    float*       out     = (float*)d_out;           // [32]

    const int M = BB * TT;  // 32768

    __nv_bfloat16 *xb, *w1t, *w2t, *hb;
    float* logits;
    cudaGetSymbolAddress((void**)&xb,     g_Xb);
    cudaGetSymbolAddress((void**)&w1t,    g_W1t);
    cudaGetSymbolAddress((void**)&w2t,    g_W2t);
    cudaGetSymbolAddress((void**)&hb,     g_hb);
    cudaGetSymbolAddress((void**)&logits, g_logits);

    f2bf_kernel<<<(M * HH) / (256 * 4), 256>>>(X, xb, M * HH);
    f2bfT_kernel<<<dim3(HH / 32, HH / 32), 256>>>(W1, w1t, HH, HH);
    f2bfT_kernel<<<dim3(VV / 32, HH / 32), 256>>>(W2, w2t, HH, VV);

    cudaFuncSetAttribute(gemm_cp<HH, 1>, cudaFuncAttributeMaxDynamicSharedMemorySize, GSM);
    cudaFuncSetAttribute(gemm_cp<VV, 0>, cudaFuncAttributeMaxDynamicSharedMemorySize, GSM);

    gemm_cp<HH, 1><<<dim3(HH / 128, M / 128), 256, GSM>>>(xb, w1t, b1, hb, nullptr);
    gemm_cp<VV, 0><<<dim3(VV / 128, M / 128), 256, GSM>>>(hb, w2t, b2, nullptr, logits);

    lse_gather_kernel<<<M / 8, 256>>>(targets);

    ctc_lin_kernel<<<BB, 32>>>(targets, ilen, out);
}

// round 7
// speedup vs baseline: 3.8796x; 1.0294x over previous
#include <cuda_runtime.h>
#include <cuda_bf16.h>
#include <math.h>
#include <stdint.h>

// Problem constants
#define BB 32
#define TT 1024
#define HH 512
#define VV 1024
#define SS 128
#define LL 257          // 2*S + 1
#define PST 132         // compact p row stride: 128 odd probs + blank + pad

// GEMM tile config
#define BK 64
#define ASTR 72                      // halves per padded tile row (144 B)
#define TILE_H (128 * ASTR)          // halves per tile
#define NSTG 3
#define STG_B (2 * TILE_H * 2)       // bytes per stage (A+B) = 36864
#define GSM (NSTG * STG_B)           // 110592 bytes dynamic smem

// Scratch (device globals: allocation-free per harness rules)
__device__ __nv_bfloat16 g_Xb[(size_t)BB * TT * HH];   // 32 MB : X bf16 (K-major)
__device__ __nv_bfloat16 g_W1t[(size_t)HH * HH];       // W1^T bf16 [N][K]
__device__ __nv_bfloat16 g_W2t[(size_t)VV * HH];       // W2^T bf16 [N][K]
__device__ __nv_bfloat16 g_hb[(size_t)BB * TT * HH];   // 32 MB : tanh(X@W1+b1) bf16
__device__ float g_logits[(size_t)BB * TT * VV];       // 128 MB: h@W2+b2
__device__ float g_p2[(size_t)BB * TT * PST + 64];     // 17 MB : compact probs

// ---------------------------------------------------------------------------
// PTX helpers
// ---------------------------------------------------------------------------
__device__ __forceinline__ unsigned su32(const void* p) {
    unsigned a;
    asm("{ .reg .u64 t; cvta.to.shared.u64 t, %1; cvt.u32.u64 %0, t; }" : "=r"(a) : "l"(p));
    return a;
}
__device__ __forceinline__ void cp16(unsigned dst, const void* src) {
    asm volatile("cp.async.cg.shared.global [%0], [%1], 16;" :: "r"(dst), "l"(src));
}
__device__ __forceinline__ void cp_commit() { asm volatile("cp.async.commit_group;" ::: "memory"); }
__device__ __forceinline__ void cp_wait2()  { asm volatile("cp.async.wait_group 2;" ::: "memory"); }
__device__ __forceinline__ void cp_wait1()  { asm volatile("cp.async.wait_group 1;" ::: "memory"); }
__device__ __forceinline__ void cp_wait0()  { asm volatile("cp.async.wait_group 0;" ::: "memory"); }

__device__ __forceinline__ void ldm_x4(unsigned* r, unsigned addr) {
    asm volatile("ldmatrix.sync.aligned.m8n8.x4.shared.b16 {%0,%1,%2,%3}, [%4];"
        : "=r"(r[0]), "=r"(r[1]), "=r"(r[2]), "=r"(r[3]) : "r"(addr));
}
__device__ __forceinline__ void mma16816(float* c, const unsigned* a, const unsigned* b) {
    asm volatile(
        "mma.sync.aligned.m16n8k16.row.col.f32.bf16.bf16.f32 "
        "{%0,%1,%2,%3}, {%4,%5,%6,%7}, {%8,%9}, {%0,%1,%2,%3};"
        : "+f"(c[0]), "+f"(c[1]), "+f"(c[2]), "+f"(c[3])
        : "r"(a[0]), "r"(a[1]), "r"(a[2]), "r"(a[3]), "r"(b[0]), "r"(b[1]));
}

// ---------------------------------------------------------------------------
// Conversion kernels
// ---------------------------------------------------------------------------
__global__ void __launch_bounds__(256)
f2bf_kernel(const float* __restrict__ in, __nv_bfloat16* __restrict__ out, int n) {
    int i = (blockIdx.x * 256 + threadIdx.x) * 4;
    if (i < n) {
        float4 v = *reinterpret_cast<const float4*>(in + i);
        *reinterpret_cast<__nv_bfloat162*>(out + i)     = __floats2bfloat162_rn(v.x, v.y);
        *reinterpret_cast<__nv_bfloat162*>(out + i + 2) = __floats2bfloat162_rn(v.z, v.w);
    }
}

// transpose + convert: in [K][N] fp32 row-major -> out [N][K] bf16 row-major
__global__ void __launch_bounds__(256)
f2bfT_kernel(const float* __restrict__ in, __nv_bfloat16* __restrict__ out, int K, int N) {
    __shared__ float tile[32][33];
    const int n0 = blockIdx.x * 32, k0 = blockIdx.y * 32;
    const int tx = threadIdx.x & 31, ty = threadIdx.x >> 5;
#pragma unroll
    for (int i = 0; i < 32; i += 8)
        tile[ty + i][tx] = in[(size_t)(k0 + ty + i) * N + n0 + tx];
    __syncthreads();
#pragma unroll
    for (int i = 0; i < 32; i += 8)
        out[(size_t)(n0 + ty + i) * K + k0 + tx] = __float2bfloat16(tile[tx][ty + i]);
}

// ---------------------------------------------------------------------------
// Pipelined bf16 mma.sync GEMM with ldmatrix: C = act(A[M,512] @ BT[N,512]^T + b)
// 128x128 tile, BK=64, 3-stage cp.async, 8 warps (4x2), warp tile 32x64.
// ---------------------------------------------------------------------------
template <int N, int TANH>
__global__ void __launch_bounds__(256)
gemm_cp(const __nv_bfloat16* __restrict__ A, const __nv_bfloat16* __restrict__ BT,
        const float* __restrict__ bias, __nv_bfloat16* __restrict__ Cb,
        float* __restrict__ Cf) {
    extern __shared__ __align__(16) __nv_bfloat16 sm[];
    const unsigned sbase = su32(sm);

    const int tid  = threadIdx.x;
    const int lane = tid & 31;
    const int warp = tid >> 5;
    const int wm   = warp & 3;
    const int wn   = warp >> 2;
    const int gid  = lane >> 2;
    const int tig  = lane & 3;

    const int row0 = blockIdx.y * 128;
    const int col0 = blockIdx.x * 128;

    // ldmatrix per-lane byte offsets within a stage's A / B tile
    unsigned aoff[2], boff[4];
    {
        const int l8  = lane & 7;
        const int j   = lane >> 3;          // matrix index 0..3
#pragma unroll
        for (int mt = 0; mt < 2; mt++) {
            const int r = wm * 32 + mt * 16 + (j & 1) * 8 + l8;
            const int k = (j >> 1) * 8;
            aoff[mt] = (unsigned)((r * ASTR + k) * 2);
        }
#pragma unroll
        for (int np = 0; np < 4; np++) {
            const int r = wn * 64 + np * 16 + (j >> 1) * 8 + l8;
            const int k = (j & 1) * 8;
            boff[np] = (unsigned)((r * ASTR + k) * 2);
        }
    }

    // cp.async fill map: thread -> tile row (tid>>1), 4 granules of 16B
    const int frow = tid >> 1;
    const int fg0  = (tid & 1) * 4;
    const __nv_bfloat16* Ap = A  + (size_t)(row0 + frow) * HH;
    const __nv_bfloat16* Bp = BT + (size_t)(col0 + frow) * HH;

    auto issue = [&](int c) {
        const unsigned abase = sbase + (unsigned)(c % NSTG) * STG_B;
        const unsigned bbase = abase + TILE_H * 2u;
        const unsigned rowoff = (unsigned)(frow * ASTR * 2);
        const int k0 = c * BK;
#pragma unroll
        for (int g = 0; g < 4; g++) {
            const int kk = (fg0 + g) * 8;
            cp16(abase + rowoff + (unsigned)(fg0 + g) * 16u, Ap + k0 + kk);
            cp16(bbase + rowoff + (unsigned)(fg0 + g) * 16u, Bp + k0 + kk);
        }
        cp_commit();
    };

    float acc[2][8][4];
#pragma unroll
    for (int mt = 0; mt < 2; mt++)
#pragma unroll
        for (int nt = 0; nt < 8; nt++)
#pragma unroll
            for (int e = 0; e < 4; e++) acc[mt][nt][e] = 0.f;

    issue(0); issue(1); issue(2);

    const int NC = HH / BK;   // 8 chunks
#pragma unroll 1
    for (int c = 0; c < NC; ++c) {
        if (c <= NC - 3)      cp_wait2();
        else if (c == NC - 2) cp_wait1();
        else                  cp_wait0();
        __syncthreads();

        const unsigned Au = sbase + (unsigned)(c % NSTG) * STG_B;
        const unsigned Bu = Au + TILE_H * 2u;

#pragma unroll
        for (int kk = 0; kk < BK / 16; kk++) {
            const unsigned kbb = (unsigned)(kk * 32);   // kb*2 bytes
            unsigned af[2][4];
            ldm_x4(af[0], Au + aoff[0] + kbb);
            ldm_x4(af[1], Au + aoff[1] + kbb);
            unsigned bf[4][4];
#pragma unroll
            for (int np = 0; np < 4; np++)
                ldm_x4(bf[np], Bu + boff[np] + kbb);
#pragma unroll
            for (int mt = 0; mt < 2; mt++)
#pragma unroll
                for (int nt = 0; nt < 8; nt++)
                    mma16816(acc[mt][nt], af[mt], &bf[nt >> 1][(nt & 1) * 2]);
        }
        __syncthreads();
        if (c + NSTG < NC) issue(c + NSTG);
    }

    // epilogue
#pragma unroll
    for (int mt = 0; mt < 2; mt++) {
#pragma unroll
        for (int nt = 0; nt < 8; nt++) {
            const int col = col0 + wn * 64 + nt * 8 + tig * 2;
            const float bx = bias[col], by = bias[col + 1];
            const int r0 = row0 + wm * 32 + mt * 16 + gid;
            const int r1 = r0 + 8;
            float v0 = acc[mt][nt][0] + bx;
            float v1 = acc[mt][nt][1] + by;
            float v2 = acc[mt][nt][2] + bx;
            float v3 = acc[mt][nt][3] + by;
            if (TANH) {
                __nv_bfloat162 p01 = __floats2bfloat162_rn(tanhf(v0), tanhf(v1));
                __nv_bfloat162 p23 = __floats2bfloat162_rn(tanhf(v2), tanhf(v3));
                *reinterpret_cast<__nv_bfloat162*>(Cb + (size_t)r0 * N + col) = p01;
                *reinterpret_cast<__nv_bfloat162*>(Cb + (size_t)r1 * N + col) = p23;
            } else {
                *reinterpret_cast<float2*>(Cf + (size_t)r0 * N + col) = make_float2(v0, v1);
                *reinterpret_cast<float2*>(Cf + (size_t)r1 * N + col) = make_float2(v2, v3);
            }
        }
    }
}

// ---------------------------------------------------------------------------
// Warp-per-row logsumexp + compact gather:
//   p2[row][i]   = exp(logit[tg[i]] - lse)  for i in [0,128)  (odd states)
//   p2[row][128] = exp(logit[0] - lse)                         (blank)
// ---------------------------------------------------------------------------
__global__ void __launch_bounds__(256)
lse_gather_kernel(const int* __restrict__ targets) {
    const int warp = threadIdx.x >> 5;
    const int lane = threadIdx.x & 31;
    const int row  = (blockIdx.x << 3) + warp;       // b*T + t
    const float* lr = g_logits + (size_t)row * VV;

    float4 v[8];
#pragma unroll
    for (int i = 0; i < 8; i++)
        v[i] = *reinterpret_cast<const float4*>(lr + (i * 128) + lane * 4);

    float m = -INFINITY;
#pragma unroll
    for (int i = 0; i < 8; i++)
        m = fmaxf(m, fmaxf(fmaxf(v[i].x, v[i].y), fmaxf(v[i].z, v[i].w)));
#pragma unroll
    for (int o = 16; o > 0; o >>= 1) m = fmaxf(m, __shfl_xor_sync(0xffffffffu, m, o));

    float s = 0.f;
#pragma unroll
    for (int i = 0; i < 8; i++)
        s += __expf(v[i].x - m) + __expf(v[i].y - m) + __expf(v[i].z - m) + __expf(v[i].w - m);
#pragma unroll
    for (int o = 16; o > 0; o >>= 1) s += __shfl_xor_sync(0xffffffffu, s, o);

    const float lse = m + logf(s);

    const int b = row >> 10;                         // T = 1024
    const int* tg = targets + (b << 7);              // S = 128
    float* pr = g_p2 + (size_t)row * PST;
#pragma unroll
    for (int it = 0; it < 4; it++) {
        const int i = it * 32 + lane;
        pr[i] = expf(lr[tg[i]] - lse);
    }
    if (lane == 0) pr[128] = expf(lr[0] - lse);      // blank
}

// ---------------------------------------------------------------------------
// Linear-domain CTC forward scan: one WARP per batch element.
// 8 contiguous states per lane (+ state 256 on lane 31); even states share the
// per-row blank probability. Renorm to 2^60 every 8 steps.
// ---------------------------------------------------------------------------
__global__ void __launch_bounds__(32)
ctc_lin_kernel(const int* __restrict__ targets, const int* __restrict__ input_lengths,
               float* __restrict__ out) {
    const int b    = blockIdx.x;
    const int lane = threadIdx.x;
    const int* tg  = targets + b * SS;
    const float* base = g_p2 + (size_t)b * TT * PST;
    const int Tlen = input_lengths[b];

    // skip coefficients for odd states j=1,3,5,7 (s = lane*8+j)
    float c1 = 0.f, c3 = 0.f, c5 = 0.f, c7 = 0.f;
    {
        const int s1 = lane * 8 + 1;
        if (s1 >= 3)            c1 = (tg[s1 >> 1] != tg[(s1 >> 1) - 1]) ? 1.f : 0.f;
        const int s3 = lane * 8 + 3;
        c3 = (tg[s3 >> 1] != tg[(s3 >> 1) - 1]) ? 1.f : 0.f;
        const int s5 = lane * 8 + 5;
        c5 = (tg[s5 >> 1] != tg[(s5 >> 1) - 1]) ? 1.f : 0.f;
        const int s7 = lane * 8 + 7;
        c7 = (tg[s7 >> 1] != tg[(s7 >> 1) - 1]) ? 1.f : 0.f;
    }

    const float init_sc = __int_as_float((100 + 127) << 23);
    float r[9];
#pragma unroll
    for (int j = 0; j < 9; j++) r[j] = 0.f;
    if (lane == 0) {
        r[0] = base[128] * init_sc;   // s=0 blank
        r[1] = base[0]   * init_sc;   // s=1 first label
    }
    int Esum = 100;

    float4 F0, F1, F2, F3;
    float  P0, P1, P2, P3;

#define LOADSLOT(Ff, Pf, tp_) do {                                            \
        int tp = (tp_); if (tp > Tlen - 1) tp = Tlen - 1;                     \
        const float* rp = base + (size_t)tp * PST;                            \
        Ff = *reinterpret_cast<const float4*>(rp + lane * 4);                 \
        Pf = rp[128];                                                         \
    } while (0)

// s-1 for j=0 AND s-2 for j=1 are BOTH the previous lane's r[7] (= u1).
#define STEP(Ff, Pf) do {                                                     \
        float u1 = __shfl_up_sync(0xffffffffu, r[7], 1);                      \
        if (lane == 0) u1 = 0.f;                                              \
        float n0 = (r[0] + u1) * Pf;                                          \
        float n1 = fmaf(c1, u1,   r[1] + r[0]) * Ff.x;                        \
        float n2 = (r[2] + r[1]) * Pf;                                        \
        float n3 = fmaf(c3, r[1], r[3] + r[2]) * Ff.y;                        \
        float n4 = (r[4] + r[3]) * Pf;                                        \
        float n5 = fmaf(c5, r[3], r[5] + r[4]) * Ff.z;                        \
        float n6 = (r[6] + r[5]) * Pf;                                        \
        float n7 = fmaf(c7, r[5], r[7] + r[6]) * Ff.w;                        \
        float n8 = (r[8] + r[7]) * Pf;                                        \
        r[0]=n0; r[1]=n1; r[2]=n2; r[3]=n3; r[4]=n4;                          \
        r[5]=n5; r[6]=n6; r[7]=n7;                                            \
        r[8] = (lane == 31) ? n8 : 0.f;                                       \
    } while (0)

#define RENORM() do {                                                         \
        float m = r[0];                                                       \
        m = fmaxf(m, r[1]); m = fmaxf(m, r[2]); m = fmaxf(m, r[3]);           \
        m = fmaxf(m, r[4]); m = fmaxf(m, r[5]); m = fmaxf(m, r[6]);           \
        m = fmaxf(m, r[7]); m = fmaxf(m, r[8]);                               \
        m = fmaxf(m, __shfl_xor_sync(0xffffffffu, m, 16));                    \
        m = fmaxf(m, __shfl_xor_sync(0xffffffffu, m, 8));                     \
        m = fmaxf(m, __shfl_xor_sync(0xffffffffu, m, 4));                     \
        m = fmaxf(m, __shfl_xor_sync(0xffffffffu, m, 2));                     \
        m = fmaxf(m, __shfl_xor_sync(0xffffffffu, m, 1));                     \
        int ex = (__float_as_int(m) >> 23) & 255;                             \
        int se = 60 - (ex - 127);                                             \
        se = (se > 127) ? 127 : ((se < -126) ? -126 : se);                    \
        const float sc = __int_as_float((se + 127) << 23);                    \
        r[0]*=sc; r[1]*=sc; r[2]*=sc; r[3]*=sc; r[4]*=sc;                     \
        r[5]*=sc; r[6]*=sc; r[7]*=sc; r[8]*=sc;                               \
        Esum += se;                                                           \
    } while (0)

    int t = 1;
    LOADSLOT(F0, P0, 1);
    LOADSLOT(F1, P1, 2);
    LOADSLOT(F2, P2, 3);
    LOADSLOT(F3, P3, 4);

    if (Tlen > 1) {
        for (;;) {
            STEP(F0, P0); LOADSLOT(F0, P0, t + 4);
            if (++t >= Tlen) break;
            if ((t & 7) == 0) RENORM();
            STEP(F1, P1); LOADSLOT(F1, P1, t + 4);
            if (++t >= Tlen) break;
            if ((t & 7) == 0) RENORM();
            STEP(F2, P2); LOADSLOT(F2, P2, t + 4);
            if (++t >= Tlen) break;
            if ((t & 7) == 0) RENORM();
            STEP(F3, P3); LOADSLOT(F3, P3, t + 4);
            if (++t >= Tlen) break;
            if ((t & 7) == 0) RENORM();
        }
    }

    __shared__ float fin[260];
#pragma unroll
    for (int j = 0; j < 8; j++) fin[lane * 8 + j] = r[j];
    if (lane == 31) fin[256] = r[8];
    __syncwarp();

    int cnt = 0;
#pragma unroll
    for (int i = 0; i < 4; i++) cnt += (tg[lane + i * 32] != 0);
#pragma unroll
    for (int o = 16; o > 0; o >>= 1) cnt += __shfl_xor_sync(0xffffffffu, cnt, o);
    const int sb = cnt;

    if (lane == 0) {
        const float e = fin[2 * sb - 1] + fin[2 * sb];
        out[b] = ((float)Esum * 0.6931471805599453f - logf(e)) / (float)sb;
    }
}

// ---------------------------------------------------------------------------
extern "C" void kernel_launch(void* const* d_in, const int* in_sizes, int n_in,
                              void* d_out, int out_size) {
    const int*   targets = (const int*)  d_in[0];
    const float* X       = (const float*)d_in[1];
    const int*   ilen    = (const int*)  d_in[2];
    const float* W1      = (const float*)d_in[3];
    const float* b1      = (const float*)d_in[4];
    const float* W2      = (const float*)d_in[5];
    const float* b2      = (const float*)d_in[6];
    float*       out     = (float*)d_out;

    const int M = BB * TT;  // 32768

    __nv_bfloat16 *xb, *w1t, *w2t, *hb;
    float* logits;
    cudaGetSymbolAddress((void**)&xb,     g_Xb);
    cudaGetSymbolAddress((void**)&w1t,    g_W1t);
    cudaGetSymbolAddress((void**)&w2t,    g_W2t);
    cudaGetSymbolAddress((void**)&hb,     g_hb);
    cudaGetSymbolAddress((void**)&logits, g_logits);

    f2bf_kernel<<<(M * HH) / (256 * 4), 256>>>(X, xb, M * HH);
    f2bfT_kernel<<<dim3(HH / 32, HH / 32), 256>>>(W1, w1t, HH, HH);
    f2bfT_kernel<<<dim3(VV / 32, HH / 32), 256>>>(W2, w2t, HH, VV);

    cudaFuncSetAttribute(gemm_cp<HH, 1>, cudaFuncAttributeMaxDynamicSharedMemorySize, GSM);
    cudaFuncSetAttribute(gemm_cp<VV, 0>, cudaFuncAttributeMaxDynamicSharedMemorySize, GSM);

    gemm_cp<HH, 1><<<dim3(HH / 128, M / 128), 256, GSM>>>(xb, w1t, b1, hb, nullptr);
    gemm_cp<VV, 0><<<dim3(VV / 128, M / 128), 256, GSM>>>(hb, w2t, b2, nullptr, logits);

    lse_gather_kernel<<<M / 8, 256>>>(targets);

    ctc_lin_kernel<<<BB, 32>>>(targets, ilen, out);
}

// round 9
// speedup vs baseline: 3.9356x; 1.0144x over previous
#include <cuda_runtime.h>
#include <cuda_bf16.h>
#include <math.h>
#include <stdint.h>

// Problem constants
#define BB 32
#define TT 1024
#define HH 512
#define VV 1024
#define SS 128
#define LL 257          // 2*S + 1
#define PST 132         // compact p row stride: 128 odd probs + blank + pad

// GEMM tile config
#define BK 64
#define ASTR 72                      // halves per padded tile row (144 B)
#define TILE_H (128 * ASTR)          // halves per tile
#define NSTG 3
#define STG_B (2 * TILE_H * 2)       // bytes per stage (A+B) = 36864
#define GSM (NSTG * STG_B)           // 110592 bytes dynamic smem

// Scratch (device globals: allocation-free per harness rules)
__device__ __nv_bfloat16 g_Xb[(size_t)BB * TT * HH];   // 32 MB : X bf16 (K-major)
__device__ __nv_bfloat16 g_W1t[(size_t)HH * HH];       // W1^T bf16 [N][K]
__device__ __nv_bfloat16 g_W2t[(size_t)VV * HH];       // W2^T bf16 [N][K]
__device__ __nv_bfloat16 g_hb[(size_t)BB * TT * HH];   // 32 MB : tanh(X@W1+b1) bf16
__device__ float g_logits[(size_t)BB * TT * VV];       // 128 MB: h@W2+b2
__device__ float2 g_part[(size_t)BB * TT][16];         // 4 MB  : per-row (max, sumexp) partials
__device__ float g_p2[(size_t)BB * TT * PST + 64];     // 17 MB : compact probs

// ---------------------------------------------------------------------------
// PTX helpers
// ---------------------------------------------------------------------------
__device__ __forceinline__ unsigned su32(const void* p) {
    unsigned a;
    asm("{ .reg .u64 t; cvta.to.shared.u64 t, %1; cvt.u32.u64 %0, t; }" : "=r"(a) : "l"(p));
    return a;
}
__device__ __forceinline__ void cp16(unsigned dst, const void* src) {
    asm volatile("cp.async.cg.shared.global [%0], [%1], 16;" :: "r"(dst), "l"(src));
}
__device__ __forceinline__ void cp_commit() { asm volatile("cp.async.commit_group;" ::: "memory"); }
__device__ __forceinline__ void cp_wait1()  { asm volatile("cp.async.wait_group 1;" ::: "memory"); }
__device__ __forceinline__ void cp_wait0()  { asm volatile("cp.async.wait_group 0;" ::: "memory"); }

__device__ __forceinline__ void ldm_x4(unsigned* r, unsigned addr) {
    asm volatile("ldmatrix.sync.aligned.m8n8.x4.shared.b16 {%0,%1,%2,%3}, [%4];"
        : "=r"(r[0]), "=r"(r[1]), "=r"(r[2]), "=r"(r[3]) : "r"(addr));
}
__device__ __forceinline__ void mma16816(float* c, const unsigned* a, const unsigned* b) {
    asm volatile(
        "mma.sync.aligned.m16n8k16.row.col.f32.bf16.bf16.f32 "
        "{%0,%1,%2,%3}, {%4,%5,%6,%7}, {%8,%9}, {%0,%1,%2,%3};"
        : "+f"(c[0]), "+f"(c[1]), "+f"(c[2]), "+f"(c[3])
        : "r"(a[0]), "r"(a[1]), "r"(a[2]), "r"(a[3]), "r"(b[0]), "r"(b[1]));
}
__device__ __forceinline__ float tanh_fast(float x) {
    float y;
    asm("tanh.approx.f32 %0, %1;" : "=f"(y) : "f"(x));
    return y;
}

// ---------------------------------------------------------------------------
// Conversion kernels
// ---------------------------------------------------------------------------
__global__ void __launch_bounds__(256)
f2bf_kernel(const float* __restrict__ in, __nv_bfloat16* __restrict__ out, int n) {
    int i = (blockIdx.x * 256 + threadIdx.x) * 4;
    if (i < n) {
        float4 v = *reinterpret_cast<const float4*>(in + i);
        *reinterpret_cast<__nv_bfloat162*>(out + i)     = __floats2bfloat162_rn(v.x, v.y);
        *reinterpret_cast<__nv_bfloat162*>(out + i + 2) = __floats2bfloat162_rn(v.z, v.w);
    }
}

// transpose + convert: in [K][N] fp32 row-major -> out [N][K] bf16 row-major
__global__ void __launch_bounds__(256)
f2bfT_kernel(const float* __restrict__ in, __nv_bfloat16* __restrict__ out, int K, int N) {
    __shared__ float tile[32][33];
    const int n0 = blockIdx.x * 32, k0 = blockIdx.y * 32;
    const int tx = threadIdx.x & 31, ty = threadIdx.x >> 5;
#pragma unroll
    for (int i = 0; i < 32; i += 8)
        tile[ty + i][tx] = in[(size_t)(k0 + ty + i) * N + n0 + tx];
    __syncthreads();
#pragma unroll
    for (int i = 0; i < 32; i += 8)
        out[(size_t)(n0 + ty + i) * K + k0 + tx] = __float2bfloat16(tile[tx][ty + i]);
}

// ---------------------------------------------------------------------------
// Pipelined bf16 mma.sync GEMM: C = act(A[M,512] @ BT[N,512]^T + bias)
// 128x128 tile, BK=64, 3-stage cp.async, SINGLE barrier per chunk
// (issue of chunk c+2 precedes compute of chunk c; slots differ mod 3).
// PART: also emit per-(row, 64-col span) (max, sumexp) partials for lse.
// ---------------------------------------------------------------------------
template <int N, int TANH, int PART>
__global__ void __launch_bounds__(256)
gemm_cp(const __nv_bfloat16* __restrict__ A, const __nv_bfloat16* __restrict__ BT,
        const float* __restrict__ bias, __nv_bfloat16* __restrict__ Cb,
        float* __restrict__ Cf) {
    extern __shared__ __align__(16) __nv_bfloat16 sm[];
    const unsigned sbase = su32(sm);

    const int tid  = threadIdx.x;
    const int lane = tid & 31;
    const int warp = tid >> 5;
    const int wm   = warp & 3;
    const int wn   = warp >> 2;
    const int gid  = lane >> 2;
    const int tig  = lane & 3;

    const int row0 = blockIdx.y * 128;
    const int col0 = blockIdx.x * 128;

    // ldmatrix per-lane byte offsets within a stage's A / B tile
    unsigned aoff[2], boff[4];
    {
        const int l8  = lane & 7;
        const int j   = lane >> 3;
#pragma unroll
        for (int mt = 0; mt < 2; mt++) {
            const int r = wm * 32 + mt * 16 + (j & 1) * 8 + l8;
            const int k = (j >> 1) * 8;
            aoff[mt] = (unsigned)((r * ASTR + k) * 2);
        }
#pragma unroll
        for (int np = 0; np < 4; np++) {
            const int r = wn * 64 + np * 16 + (j >> 1) * 8 + l8;
            const int k = (j & 1) * 8;
            boff[np] = (unsigned)((r * ASTR + k) * 2);
        }
    }

    // cp.async fill map: thread -> tile row (tid>>1), 4 granules of 16B
    const int frow = tid >> 1;
    const int fg0  = (tid & 1) * 4;
    const __nv_bfloat16* Ap = A  + (size_t)(row0 + frow) * HH;
    const __nv_bfloat16* Bp = BT + (size_t)(col0 + frow) * HH;

    auto issue = [&](int c) {
        const unsigned abase = sbase + (unsigned)(c % NSTG) * STG_B;
        const unsigned bbase = abase + TILE_H * 2u;
        const unsigned rowoff = (unsigned)(frow * ASTR * 2);
        const int k0 = c * BK;
#pragma unroll
        for (int g = 0; g < 4; g++) {
            const int kk = (fg0 + g) * 8;
            cp16(abase + rowoff + (unsigned)(fg0 + g) * 16u, Ap + k0 + kk);
            cp16(bbase + rowoff + (unsigned)(fg0 + g) * 16u, Bp + k0 + kk);
        }
        cp_commit();
    };

    float acc[2][8][4];
#pragma unroll
    for (int mt = 0; mt < 2; mt++)
#pragma unroll
        for (int nt = 0; nt < 8; nt++)
#pragma unroll
            for (int e = 0; e < 4; e++) acc[mt][nt][e] = 0.f;

    issue(0); issue(1);

    const int NC = HH / BK;   // 8 chunks
#pragma unroll 1
    for (int c = 0; c < NC; ++c) {
        if (c < NC - 1) cp_wait1(); else cp_wait0();
        __syncthreads();
        if (c + 2 < NC) issue(c + 2);

        const unsigned Au = sbase + (unsigned)(c % NSTG) * STG_B;
        const unsigned Bu = Au + TILE_H * 2u;

#pragma unroll
        for (int kk = 0; kk < BK / 16; kk++) {
            const unsigned kbb = (unsigned)(kk * 32);
            unsigned af[2][4];
            ldm_x4(af[0], Au + aoff[0] + kbb);
            ldm_x4(af[1], Au + aoff[1] + kbb);
            unsigned bf[4][4];
#pragma unroll
            for (int np = 0; np < 4; np++)
                ldm_x4(bf[np], Bu + boff[np] + kbb);
#pragma unroll
            for (int mt = 0; mt < 2; mt++)
#pragma unroll
                for (int nt = 0; nt < 8; nt++)
                    mma16816(acc[mt][nt], af[mt], &bf[nt >> 1][(nt & 1) * 2]);
        }
    }

    // add bias in place (logits now complete in registers)
#pragma unroll
    for (int mt = 0; mt < 2; mt++)
#pragma unroll
        for (int nt = 0; nt < 8; nt++) {
            const int col = col0 + wn * 64 + nt * 8 + tig * 2;
            const float bx = bias[col], by = bias[col + 1];
            acc[mt][nt][0] += bx; acc[mt][nt][1] += by;
            acc[mt][nt][2] += bx; acc[mt][nt][3] += by;
        }

    // store
#pragma unroll
    for (int mt = 0; mt < 2; mt++) {
#pragma unroll
        for (int nt = 0; nt < 8; nt++) {
            const int col = col0 + wn * 64 + nt * 8 + tig * 2;
            const int r0 = row0 + wm * 32 + mt * 16 + gid;
            const int r1 = r0 + 8;
            if (TANH) {
                __nv_bfloat162 p01 = __floats2bfloat162_rn(tanh_fast(acc[mt][nt][0]),
                                                           tanh_fast(acc[mt][nt][1]));
                __nv_bfloat162 p23 = __floats2bfloat162_rn(tanh_fast(acc[mt][nt][2]),
                                                           tanh_fast(acc[mt][nt][3]));
                *reinterpret_cast<__nv_bfloat162*>(Cb + (size_t)r0 * N + col) = p01;
                *reinterpret_cast<__nv_bfloat162*>(Cb + (size_t)r1 * N + col) = p23;
            } else {
                *reinterpret_cast<float2*>(Cf + (size_t)r0 * N + col) =
                    make_float2(acc[mt][nt][0], acc[mt][nt][1]);
                *reinterpret_cast<float2*>(Cf + (size_t)r1 * N + col) =
                    make_float2(acc[mt][nt][2], acc[mt][nt][3]);
            }
        }
    }

    // per-row (max, sumexp) partials over this warp's 64-col span
    if (PART) {
#pragma unroll
        for (int mt = 0; mt < 2; mt++) {
#pragma unroll
            for (int half = 0; half < 2; half++) {
                float m = -INFINITY;
#pragma unroll
                for (int nt = 0; nt < 8; nt++)
                    m = fmaxf(m, fmaxf(acc[mt][nt][half * 2], acc[mt][nt][half * 2 + 1]));
                float s = 0.f;
#pragma unroll
                for (int nt = 0; nt < 8; nt++)
                    s += __expf(acc[mt][nt][half * 2] - m) + __expf(acc[mt][nt][half * 2 + 1] - m);
                // combine across tig (lanes gid*4 + 0..3)
#pragma unroll
                for (int o = 1; o <= 2; o <<= 1) {
                    const float mo = __shfl_xor_sync(0xffffffffu, m, o);
                    const float so = __shfl_xor_sync(0xffffffffu, s, o);
                    const float mn = fmaxf(m, mo);
                    s = s * __expf(m - mn) + so * __expf(mo - mn);
                    m = mn;
                }
                if (tig == 0) {
                    const int row = row0 + wm * 32 + mt * 16 + gid + half * 8;
                    g_part[row][blockIdx.x * 2 + wn] = make_float2(m, s);
                }
            }
        }
    }
}

// ---------------------------------------------------------------------------
// lse from partials + compact gather (warp per row, 8 rows per block):
//   p2[row][i]   = exp(logit[tg[i]] - lse)  for i in [0,128)  (odd states)
//   p2[row][128] = exp(logit[0] - lse)                         (blank)
// ---------------------------------------------------------------------------
__global__ void __launch_bounds__(256)
lse_gather_kernel(const int* __restrict__ targets) {
    const int warp = threadIdx.x >> 5;
    const int lane = threadIdx.x & 31;
    const int row  = (blockIdx.x << 3) + warp;       // b*T + t

    float m = -INFINITY, s = 0.f;
    if (lane < 16) {
        const float2 p = g_part[row][lane];
        m = p.x; s = p.y;
    }
#pragma unroll
    for (int o = 16; o > 0; o >>= 1) {
        const float mo = __shfl_xor_sync(0xffffffffu, m, o);
        const float so = __shfl_xor_sync(0xffffffffu, s, o);
        const float mn = fmaxf(m, mo);
        s = s * __expf(m - mn) + so * __expf(mo - mn);
        m = mn;
    }
    const float lse = m + logf(s);

    const float* lr = g_logits + (size_t)row * VV;
    const int b = row >> 10;                         // T = 1024
    const int* tg = targets + (b << 7);              // S = 128
    float* pr = g_p2 + (size_t)row * PST;
#pragma unroll
    for (int it = 0; it < 4; it++) {
        const int i = it * 32 + lane;
        pr[i] = expf(lr[tg[i]] - lse);
    }
    if (lane == 0) pr[128] = expf(lr[0] - lse);      // blank
}

// ---------------------------------------------------------------------------
// Linear-domain CTC forward scan: one WARP per batch element.
// ---------------------------------------------------------------------------
__global__ void __launch_bounds__(32)
ctc_lin_kernel(const int* __restrict__ targets, const int* __restrict__ input_lengths,
               float* __restrict__ out) {
    const int b    = blockIdx.x;
    const int lane = threadIdx.x;
    const int* tg  = targets + b * SS;
    const float* base = g_p2 + (size_t)b * TT * PST;
    const int Tlen = input_lengths[b];

    float c1 = 0.f, c3 = 0.f, c5 = 0.f, c7 = 0.f;
    {
        const int s1 = lane * 8 + 1;
        if (s1 >= 3)            c1 = (tg[s1 >> 1] != tg[(s1 >> 1) - 1]) ? 1.f : 0.f;
        const int s3 = lane * 8 + 3;
        c3 = (tg[s3 >> 1] != tg[(s3 >> 1) - 1]) ? 1.f : 0.f;
        const int s5 = lane * 8 + 5;
        c5 = (tg[s5 >> 1] != tg[(s5 >> 1) - 1]) ? 1.f : 0.f;
        const int s7 = lane * 8 + 7;
        c7 = (tg[s7 >> 1] != tg[(s7 >> 1) - 1]) ? 1.f : 0.f;
    }

    const float init_sc = __int_as_float((100 + 127) << 23);
    float r[9];
#pragma unroll
    for (int j = 0; j < 9; j++) r[j] = 0.f;
    if (lane == 0) {
        r[0] = base[128] * init_sc;   // s=0 blank
        r[1] = base[0]   * init_sc;   // s=1 first label
    }
    int Esum = 100;

    float4 F0, F1, F2, F3;
    float  P0, P1, P2, P3;

#define LOADSLOT(Ff, Pf, tp_) do {                                            \
        int tp = (tp_); if (tp > Tlen - 1) tp = Tlen - 1;                     \
        const float* rp = base + (size_t)tp * PST;                            \
        Ff = *reinterpret_cast<const float4*>(rp + lane * 4);                 \
        Pf = rp[128];                                                         \
    } while (0)

// s-1 for j=0 AND s-2 for j=1 are BOTH the previous lane's r[7] (= u1).
#define STEP(Ff, Pf) do {                                                     \
        float u1 = __shfl_up_sync(0xffffffffu, r[7], 1);                      \
        if (lane == 0) u1 = 0.f;                                              \
        float n0 = (r[0] + u1) * Pf;                                          \
        float n1 = fmaf(c1, u1,   r[1] + r[0]) * Ff.x;                        \
        float n2 = (r[2] + r[1]) * Pf;                                        \
        float n3 = fmaf(c3, r[1], r[3] + r[2]) * Ff.y;                        \
        float n4 = (r[4] + r[3]) * Pf;                                        \
        float n5 = fmaf(c5, r[3], r[5] + r[4]) * Ff.z;                        \
        float n6 = (r[6] + r[5]) * Pf;                                        \
        float n7 = fmaf(c7, r[5], r[7] + r[6]) * Ff.w;                        \
        float n8 = (r[8] + r[7]) * Pf;                                        \
        r[0]=n0; r[1]=n1; r[2]=n2; r[3]=n3; r[4]=n4;                          \
        r[5]=n5; r[6]=n6; r[7]=n7;                                            \
        r[8] = (lane == 31) ? n8 : 0.f;                                       \
    } while (0)

#define RENORM() do {                                                         \
        float m = r[0];                                                       \
        m = fmaxf(m, r[1]); m = fmaxf(m, r[2]); m = fmaxf(m, r[3]);           \
        m = fmaxf(m, r[4]); m = fmaxf(m, r[5]); m = fmaxf(m, r[6]);           \
        m = fmaxf(m, r[7]); m = fmaxf(m, r[8]);                               \
        m = fmaxf(m, __shfl_xor_sync(0xffffffffu, m, 16));                    \
        m = fmaxf(m, __shfl_xor_sync(0xffffffffu, m, 8));                     \
        m = fmaxf(m, __shfl_xor_sync(0xffffffffu, m, 4));                     \
        m = fmaxf(m, __shfl_xor_sync(0xffffffffu, m, 2));                    \
        m = fmaxf(m, __shfl_xor_sync(0xffffffffu, m, 1));                    \
        int ex = (__float_as_int(m) >> 23) & 255;                             \
        int se = 60 - (ex - 127);                                             \
        se = (se > 127) ? 127 : ((se < -126) ? -126 : se);                    \
        const float sc = __int_as_float((se + 127) << 23);                    \
        r[0]*=sc; r[1]*=sc; r[2]*=sc; r[3]*=sc; r[4]*=sc;                     \
        r[5]*=sc; r[6]*=sc; r[7]*=sc; r[8]*=sc;                               \
        Esum += se;                                                           \
    } while (0)

    int t = 1;
    LOADSLOT(F0, P0, 1);
    LOADSLOT(F1, P1, 2);
    LOADSLOT(F2, P2, 3);
    LOADSLOT(F3, P3, 4);

    if (Tlen > 1) {
        for (;;) {
            STEP(F0, P0); LOADSLOT(F0, P0, t + 4);
            if (++t >= Tlen) break;
            if ((t & 7) == 0) RENORM();
            STEP(F1, P1); LOADSLOT(F1, P1, t + 4);
            if (++t >= Tlen) break;
            if ((t & 7) == 0) RENORM();
            STEP(F2, P2); LOADSLOT(F2, P2, t + 4);
            if (++t >= Tlen) break;
            if ((t & 7) == 0) RENORM();
            STEP(F3, P3); LOADSLOT(F3, P3, t + 4);
            if (++t >= Tlen) break;
            if ((t & 7) == 0) RENORM();
        }
    }

    __shared__ float fin[260];
#pragma unroll
    for (int j = 0; j < 8; j++) fin[lane * 8 + j] = r[j];
    if (lane == 31) fin[256] = r[8];
    __syncwarp();

    int cnt = 0;
#pragma unroll
    for (int i = 0; i < 4; i++) cnt += (tg[lane + i * 32] != 0);
#pragma unroll
    for (int o = 16; o > 0; o >>= 1) cnt += __shfl_xor_sync(0xffffffffu, cnt, o);
    const int sb = cnt;

    if (lane == 0) {
        const float e = fin[2 * sb - 1] + fin[2 * sb];
        out[b] = ((float)Esum * 0.6931471805599453f - logf(e)) / (float)sb;
    }
}

// ---------------------------------------------------------------------------
extern "C" void kernel_launch(void* const* d_in, const int* in_sizes, int n_in,
                              void* d_out, int out_size) {
    const int*   targets = (const int*)  d_in[0];
    const float* X       = (const float*)d_in[1];
    const int*   ilen    = (const int*)  d_in[2];
    const float* W1      = (const float*)d_in[3];
    const float* b1      = (const float*)d_in[4];
    const float* W2      = (const float*)d_in[5];
    const float* b2      = (const float*)d_in[6];
    float*       out     = (float*)d_out;

    const int M = BB * TT;  // 32768

    __nv_bfloat16 *xb, *w1t, *w2t, *hb;
    float* logits;
    cudaGetSymbolAddress((void**)&xb,     g_Xb);
    cudaGetSymbolAddress((void**)&w1t,    g_W1t);
    cudaGetSymbolAddress((void**)&w2t,    g_W2t);
    cudaGetSymbolAddress((void**)&hb,     g_hb);
    cudaGetSymbolAddress((void**)&logits, g_logits);

    f2bf_kernel<<<(M * HH) / (256 * 4), 256>>>(X, xb, M * HH);
    f2bfT_kernel<<<dim3(HH / 32, HH / 32), 256>>>(W1, w1t, HH, HH);
    f2bfT_kernel<<<dim3(VV / 32, HH / 32), 256>>>(W2, w2t, HH, VV);

    cudaFuncSetAttribute(gemm_cp<HH, 1, 0>, cudaFuncAttributeMaxDynamicSharedMemorySize, GSM);
    cudaFuncSetAttribute(gemm_cp<VV, 0, 1>, cudaFuncAttributeMaxDynamicSharedMemorySize, GSM);

    gemm_cp<HH, 1, 0><<<dim3(HH / 128, M / 128), 256, GSM>>>(xb, w1t, b1, hb, nullptr);
    gemm_cp<VV, 0, 1><<<dim3(VV / 128, M / 128), 256, GSM>>>(hb, w2t, b2, nullptr, logits);

    lse_gather_kernel<<<M / 8, 256>>>(targets);

    ctc_lin_kernel<<<BB, 32>>>(targets, ilen, out);
}

// round 11
// speedup vs baseline: 3.9695x; 1.0086x over previous
#include <cuda_runtime.h>
#include <cuda_bf16.h>
#include <math.h>
#include <stdint.h>

// Problem constants
#define BB 32
#define TT 1024
#define HH 512
#define VV 1024
#define SS 128
#define LL 257          // 2*S + 1
#define PST 132         // compact row stride (floats): 128 odd entries + blank + pad

// GEMM tile config
#define BK 64
#define ASTR 72                      // halves per padded tile row (144 B)
#define TILE_H (128 * ASTR)          // halves per tile
#define NSTG 3
#define STG_B (2 * TILE_H * 2)       // bytes per stage (A+B) = 36864
#define GSM (NSTG * STG_B)           // 110592 bytes dynamic smem

#define SLSTR 129                    // floats per staged-logits row (odd: conflict-light)
#define SL_BYTES (128 * SLSTR * 4)   // 66048
#define LIST_OFF SL_BYTES            // s_cnt at LIST_OFF, list ints after

// Scratch (device globals: allocation-free per harness rules)
__device__ __nv_bfloat16 g_Xb[(size_t)BB * TT * HH];   // 32 MB : X bf16 (K-major)
__device__ __nv_bfloat16 g_W1t[(size_t)HH * HH];       // W1^T bf16 [N][K]
__device__ __nv_bfloat16 g_W2t[(size_t)VV * HH];       // W2^T bf16 [N][K]
__device__ __nv_bfloat16 g_hb[(size_t)BB * TT * HH];   // 32 MB : tanh(X@W1+b1) bf16
__device__ float2 g_part[(size_t)BB * TT][16];         // 4 MB  : per-row (max, sumexp)
__device__ float g_gath[(size_t)BB * TT * PST + 64];   // 17 MB : gathered logits
__device__ float g_p2[(size_t)BB * TT * PST + 64];     // 17 MB : compact probs

// ---------------------------------------------------------------------------
// PTX helpers
// ---------------------------------------------------------------------------
__device__ __forceinline__ unsigned su32(const void* p) {
    unsigned a;
    asm("{ .reg .u64 t; cvta.to.shared.u64 t, %1; cvt.u32.u64 %0, t; }" : "=r"(a) : "l"(p));
    return a;
}
__device__ __forceinline__ void cp16(unsigned dst, const void* src) {
    asm volatile("cp.async.cg.shared.global [%0], [%1], 16;" :: "r"(dst), "l"(src));
}
__device__ __forceinline__ void cp_commit() { asm volatile("cp.async.commit_group;" ::: "memory"); }
__device__ __forceinline__ void cp_wait1()  { asm volatile("cp.async.wait_group 1;" ::: "memory"); }
__device__ __forceinline__ void cp_wait0()  { asm volatile("cp.async.wait_group 0;" ::: "memory"); }

__device__ __forceinline__ void ldm_x4(unsigned* r, unsigned addr) {
    asm volatile("ldmatrix.sync.aligned.m8n8.x4.shared.b16 {%0,%1,%2,%3}, [%4];"
        : "=r"(r[0]), "=r"(r[1]), "=r"(r[2]), "=r"(r[3]) : "r"(addr));
}
__device__ __forceinline__ void mma16816(float* c, const unsigned* a, const unsigned* b) {
    asm volatile(
        "mma.sync.aligned.m16n8k16.row.col.f32.bf16.bf16.f32 "
        "{%0,%1,%2,%3}, {%4,%5,%6,%7}, {%8,%9}, {%0,%1,%2,%3};"
        : "+f"(c[0]), "+f"(c[1]), "+f"(c[2]), "+f"(c[3])
        : "r"(a[0]), "r"(a[1]), "r"(a[2]), "r"(a[3]), "r"(b[0]), "r"(b[1]));
}
__device__ __forceinline__ float tanh_fast(float x) {
    float y;
    asm("tanh.approx.f32 %0, %1;" : "=f"(y) : "f"(x));
    return y;
}

// ---------------------------------------------------------------------------
// Conversion kernels
// ---------------------------------------------------------------------------
__global__ void __launch_bounds__(256)
f2bf_kernel(const float* __restrict__ in, __nv_bfloat16* __restrict__ out, int n) {
    int i = (blockIdx.x * 256 + threadIdx.x) * 4;
    if (i < n) {
        float4 v = *reinterpret_cast<const float4*>(in + i);
        *reinterpret_cast<__nv_bfloat162*>(out + i)     = __floats2bfloat162_rn(v.x, v.y);
        *reinterpret_cast<__nv_bfloat162*>(out + i + 2) = __floats2bfloat162_rn(v.z, v.w);
    }
}

// transpose + convert: in [K][N] fp32 row-major -> out [N][K] bf16 row-major
__global__ void __launch_bounds__(256)
f2bfT_kernel(const float* __restrict__ in, __nv_bfloat16* __restrict__ out, int K, int N) {
    __shared__ float tile[32][33];
    const int n0 = blockIdx.x * 32, k0 = blockIdx.y * 32;
    const int tx = threadIdx.x & 31, ty = threadIdx.x >> 5;
#pragma unroll
    for (int i = 0; i < 32; i += 8)
        tile[ty + i][tx] = in[(size_t)(k0 + ty + i) * N + n0 + tx];
    __syncthreads();
#pragma unroll
    for (int i = 0; i < 32; i += 8)
        out[(size_t)(n0 + ty + i) * K + k0 + tx] = __float2bfloat16(tile[tx][ty + i]);
}

// ---------------------------------------------------------------------------
// Shared GEMM mainloop: 128x128 tile, BK=64, 3-stage cp.async, single barrier
// per chunk. Leaves logits+bias in acc[2][8][4].
// ---------------------------------------------------------------------------
template <int KDIM>
struct GemmCtx {
    unsigned sbase;
    int lane, warp, wm, wn, gid, tig, row0, col0;
    unsigned aoff[2], boff[4];
    const __nv_bfloat16 *Ap, *Bp;
    int frow, fg0;

    __device__ __forceinline__ void init(const __nv_bfloat16* A, const __nv_bfloat16* BT,
                                         unsigned sb) {
        sbase = sb;
        const int tid = threadIdx.x;
        lane = tid & 31; warp = tid >> 5;
        wm = warp & 3;   wn = warp >> 2;
        gid = lane >> 2; tig = lane & 3;
        row0 = blockIdx.y * 128; col0 = blockIdx.x * 128;
        const int l8 = lane & 7, j = lane >> 3;
#pragma unroll
        for (int mt = 0; mt < 2; mt++) {
            const int r = wm * 32 + mt * 16 + (j & 1) * 8 + l8;
            aoff[mt] = (unsigned)((r * ASTR + (j >> 1) * 8) * 2);
        }
#pragma unroll
        for (int np = 0; np < 4; np++) {
            const int r = wn * 64 + np * 16 + (j >> 1) * 8 + l8;
            boff[np] = (unsigned)((r * ASTR + (j & 1) * 8) * 2);
        }
        frow = tid >> 1; fg0 = (tid & 1) * 4;
        Ap = A  + (size_t)(row0 + frow) * KDIM;
        Bp = BT + (size_t)(col0 + frow) * KDIM;
    }

    __device__ __forceinline__ void issue(int c) {
        const unsigned abase = sbase + (unsigned)(c % NSTG) * STG_B;
        const unsigned bbase = abase + TILE_H * 2u;
        const unsigned rowoff = (unsigned)(frow * ASTR * 2);
        const int k0 = c * BK;
#pragma unroll
        for (int g = 0; g < 4; g++) {
            const int kk = (fg0 + g) * 8;
            cp16(abase + rowoff + (unsigned)(fg0 + g) * 16u, Ap + k0 + kk);
            cp16(bbase + rowoff + (unsigned)(fg0 + g) * 16u, Bp + k0 + kk);
        }
        cp_commit();
    }

    __device__ __forceinline__ void run(float (&acc)[2][8][4], const float* bias) {
#pragma unroll
        for (int mt = 0; mt < 2; mt++)
#pragma unroll
            for (int nt = 0; nt < 8; nt++)
#pragma unroll
                for (int e = 0; e < 4; e++) acc[mt][nt][e] = 0.f;

        issue(0); issue(1);
        const int NC = KDIM / BK;
#pragma unroll 1
        for (int c = 0; c < NC; ++c) {
            if (c < NC - 1) cp_wait1(); else cp_wait0();
            __syncthreads();
            if (c + 2 < NC) issue(c + 2);

            const unsigned Au = sbase + (unsigned)(c % NSTG) * STG_B;
            const unsigned Bu = Au + TILE_H * 2u;
#pragma unroll
            for (int kk = 0; kk < BK / 16; kk++) {
                const unsigned kbb = (unsigned)(kk * 32);
                unsigned af[2][4];
                ldm_x4(af[0], Au + aoff[0] + kbb);
                ldm_x4(af[1], Au + aoff[1] + kbb);
                unsigned bf[4][4];
#pragma unroll
                for (int np = 0; np < 4; np++)
                    ldm_x4(bf[np], Bu + boff[np] + kbb);
#pragma unroll
                for (int mt = 0; mt < 2; mt++)
#pragma unroll
                    for (int nt = 0; nt < 8; nt++)
                        mma16816(acc[mt][nt], af[mt], &bf[nt >> 1][(nt & 1) * 2]);
            }
        }
        // add bias
#pragma unroll
        for (int mt = 0; mt < 2; mt++)
#pragma unroll
            for (int nt = 0; nt < 8; nt++) {
                const int col = col0 + wn * 64 + nt * 8 + tig * 2;
                const float bx = bias[col], by = bias[col + 1];
                acc[mt][nt][0] += bx; acc[mt][nt][1] += by;
                acc[mt][nt][2] += bx; acc[mt][nt][3] += by;
            }
    }
};

// ---------------------------------------------------------------------------
// GEMM1: h = tanh(X@W1+b1), bf16 output
// ---------------------------------------------------------------------------
__global__ void __launch_bounds__(256)
gemm1_kernel(const __nv_bfloat16* __restrict__ A, const __nv_bfloat16* __restrict__ BT,
             const float* __restrict__ bias, __nv_bfloat16* __restrict__ Cb) {
    extern __shared__ __align__(16) char smraw[];
    GemmCtx<HH> cx;
    cx.init(A, BT, su32(smraw));
    float acc[2][8][4];
    cx.run(acc, bias);

#pragma unroll
    for (int mt = 0; mt < 2; mt++)
#pragma unroll
        for (int nt = 0; nt < 8; nt++) {
            const int col = cx.col0 + cx.wn * 64 + nt * 8 + cx.tig * 2;
            const int r0 = cx.row0 + cx.wm * 32 + mt * 16 + cx.gid;
            const int r1 = r0 + 8;
            __nv_bfloat162 p01 = __floats2bfloat162_rn(tanh_fast(acc[mt][nt][0]),
                                                       tanh_fast(acc[mt][nt][1]));
            __nv_bfloat162 p23 = __floats2bfloat162_rn(tanh_fast(acc[mt][nt][2]),
                                                       tanh_fast(acc[mt][nt][3]));
            *reinterpret_cast<__nv_bfloat162*>(Cb + (size_t)r0 * HH + col) = p01;
            *reinterpret_cast<__nv_bfloat162*>(Cb + (size_t)r1 * HH + col) = p23;
        }
}

// ---------------------------------------------------------------------------
// GEMM2 fused: logits stay on-chip. Emits (max,sumexp) partials + gathered
// logit values at this CTA's target labels. NO global logits array.
// ---------------------------------------------------------------------------
__global__ void __launch_bounds__(256)
gemm2_fused(const __nv_bfloat16* __restrict__ A, const __nv_bfloat16* __restrict__ BT,
            const float* __restrict__ bias, const int* __restrict__ targets) {
    extern __shared__ __align__(16) char smraw[];
    GemmCtx<HH> cx;
    cx.init(A, BT, su32(smraw));
    float acc[2][8][4];
    cx.run(acc, bias);

    const int lane = cx.lane, warp = cx.warp, wm = cx.wm, wn = cx.wn;
    const int gid = cx.gid, tig = cx.tig, row0 = cx.row0, col0 = cx.col0;

    // ---- per-row (max, sumexp) partials over this warp's 64-col span
#pragma unroll
    for (int mt = 0; mt < 2; mt++) {
#pragma unroll
        for (int half = 0; half < 2; half++) {
            float m = -INFINITY;
#pragma unroll
            for (int nt = 0; nt < 8; nt++)
                m = fmaxf(m, fmaxf(acc[mt][nt][half * 2], acc[mt][nt][half * 2 + 1]));
            float s = 0.f;
#pragma unroll
            for (int nt = 0; nt < 8; nt++)
                s += __expf(acc[mt][nt][half * 2] - m) + __expf(acc[mt][nt][half * 2 + 1] - m);
#pragma unroll
            for (int o = 1; o <= 2; o <<= 1) {
                const float mo = __shfl_xor_sync(0xffffffffu, m, o);
                const float so = __shfl_xor_sync(0xffffffffu, s, o);
                const float mn = fmaxf(m, mo);
                s = s * __expf(m - mn) + so * __expf(mo - mn);
                m = mn;
            }
            if (tig == 0) {
                const int row = row0 + wm * 32 + mt * 16 + gid + half * 8;
                g_part[row][blockIdx.x * 2 + wn] = make_float2(m, s);
            }
        }
    }

    // ---- stage logits block to smem (pipeline stages are dead after a barrier)
    __syncthreads();
    float* sl = reinterpret_cast<float*>(smraw);
#pragma unroll
    for (int mt = 0; mt < 2; mt++)
#pragma unroll
        for (int nt = 0; nt < 8; nt++) {
            const int c = wn * 64 + nt * 8 + tig * 2;
            const int r0 = wm * 32 + mt * 16 + gid;
            const int r1 = r0 + 8;
            sl[r0 * SLSTR + c]     = acc[mt][nt][0];
            sl[r0 * SLSTR + c + 1] = acc[mt][nt][1];
            sl[r1 * SLSTR + c]     = acc[mt][nt][2];
            sl[r1 * SLSTR + c + 1] = acc[mt][nt][3];
        }

    // ---- warp 0: compact list of label indices landing in [col0, col0+128)
    const int b = row0 >> 10;                 // T = 1024, 8 tiles per batch row-block
    const int* tg = targets + (b << 7);
    int* s_cnt  = reinterpret_cast<int*>(smraw + LIST_OFF);
    int* s_list = s_cnt + 4;
    if (warp == 0) {
        int cnt = 0;
        const unsigned lt = (1u << lane) - 1u;
#pragma unroll
        for (int it = 0; it < 4; it++) {
            const int i = it * 32 + lane;
            const int lab = tg[i];
            const bool in = (lab >= col0) && (lab < col0 + 128);
            const unsigned mask = __ballot_sync(0xffffffffu, in);
            if (in) s_list[cnt + __popc(mask & lt)] = (i << 16) | (lab - col0);
            cnt += __popc(mask);
        }
        if (lane == 0) *s_cnt = cnt;
    }
    __syncthreads();
    const int cnt = *s_cnt;

    // ---- scatter gathered logits: 8 warps x 16 rows
#pragma unroll 1
    for (int rr = 0; rr < 16; rr++) {
        const int r = warp * 16 + rr;
        float* grow = g_gath + (size_t)(row0 + r) * PST;
        for (int e = lane; e < cnt; e += 32) {
            const int packed = s_list[e];
            grow[packed >> 16] = sl[r * SLSTR + (packed & 0xffff)];
        }
        if (col0 == 0 && lane == 0) grow[128] = sl[r * SLSTR];   // blank = col 0
    }
}

// ---------------------------------------------------------------------------
// lse from partials + p = exp(gath - lse). Warp per row; fully coalesced.
// ---------------------------------------------------------------------------
__global__ void __launch_bounds__(256)
lse_finish_kernel() {
    const int warp = threadIdx.x >> 5;
    const int lane = threadIdx.x & 31;
    const int row  = (blockIdx.x << 3) + warp;

    float m = -INFINITY, s = 0.f;
    if (lane < 16) {
        const float2 p = g_part[row][lane];
        m = p.x; s = p.y;
    }
#pragma unroll
    for (int o = 16; o > 0; o >>= 1) {
        const float mo = __shfl_xor_sync(0xffffffffu, m, o);
        const float so = __shfl_xor_sync(0xffffffffu, s, o);
        const float mn = fmaxf(m, mo);
        s = s * __expf(m - mn) + so * __expf(mo - mn);
        m = mn;
    }
    const float lse = m + logf(s);

    const float* gr = g_gath + (size_t)row * PST;
    float* pr = g_p2 + (size_t)row * PST;
    const float4 v = reinterpret_cast<const float4*>(gr)[lane];
    float4 p;
    p.x = expf(v.x - lse); p.y = expf(v.y - lse);
    p.z = expf(v.z - lse); p.w = expf(v.w - lse);
    reinterpret_cast<float4*>(pr)[lane] = p;
    if (lane == 0) pr[128] = expf(gr[128] - lse);
}

// ---------------------------------------------------------------------------
// Linear-domain CTC forward scan: one WARP per batch element.
// ---------------------------------------------------------------------------
__global__ void __launch_bounds__(32)
ctc_lin_kernel(const int* __restrict__ targets, const int* __restrict__ input_lengths,
               float* __restrict__ out) {
    const int b    = blockIdx.x;
    const int lane = threadIdx.x;
    const int* tg  = targets + b * SS;
    const float* base = g_p2 + (size_t)b * TT * PST;
    const int Tlen = input_lengths[b];

    float c1 = 0.f, c3 = 0.f, c5 = 0.f, c7 = 0.f;
    {
        const int s1 = lane * 8 + 1;
        if (s1 >= 3)            c1 = (tg[s1 >> 1] != tg[(s1 >> 1) - 1]) ? 1.f : 0.f;
        const int s3 = lane * 8 + 3;
        c3 = (tg[s3 >> 1] != tg[(s3 >> 1) - 1]) ? 1.f : 0.f;
        const int s5 = lane * 8 + 5;
        c5 = (tg[s5 >> 1] != tg[(s5 >> 1) - 1]) ? 1.f : 0.f;
        const int s7 = lane * 8 + 7;
        c7 = (tg[s7 >> 1] != tg[(s7 >> 1) - 1]) ? 1.f : 0.f;
    }

    const float init_sc = __int_as_float((100 + 127) << 23);
    float r[9];
#pragma unroll
    for (int j = 0; j < 9; j++) r[j] = 0.f;
    if (lane == 0) {
        r[0] = base[128] * init_sc;   // s=0 blank
        r[1] = base[0]   * init_sc;   // s=1 first label
    }
    int Esum = 100;

    float4 F0, F1, F2, F3;
    float  P0, P1, P2, P3;

#define LOADSLOT(Ff, Pf, tp_) do {                                            \
        int tp = (tp_); if (tp > Tlen - 1) tp = Tlen - 1;                     \
        const float* rp = base + (size_t)tp * PST;                            \
        Ff = *reinterpret_cast<const float4*>(rp + lane * 4);                 \
        Pf = rp[128];                                                         \
    } while (0)

#define STEP(Ff, Pf) do {                                                     \
        float u1 = __shfl_up_sync(0xffffffffu, r[7], 1);                      \
        if (lane == 0) u1 = 0.f;                                              \
        float n0 = (r[0] + u1) * Pf;                                          \
        float n1 = fmaf(c1, u1,   r[1] + r[0]) * Ff.x;                        \
        float n2 = (r[2] + r[1]) * Pf;                                        \
        float n3 = fmaf(c3, r[1], r[3] + r[2]) * Ff.y;                        \
        float n4 = (r[4] + r[3]) * Pf;                                        \
        float n5 = fmaf(c5, r[3], r[5] + r[4]) * Ff.z;                        \
        float n6 = (r[6] + r[5]) * Pf;                                        \
        float n7 = fmaf(c7, r[5], r[7] + r[6]) * Ff.w;                        \
        float n8 = (r[8] + r[7]) * Pf;                                        \
        r[0]=n0; r[1]=n1; r[2]=n2; r[3]=n3; r[4]=n4;                          \
        r[5]=n5; r[6]=n6; r[7]=n7;                                            \
        r[8] = (lane == 31) ? n8 : 0.f;                                       \
    } while (0)

#define RENORM() do {                                                         \
        float m = r[0];                                                       \
        m = fmaxf(m, r[1]); m = fmaxf(m, r[2]); m = fmaxf(m, r[3]);           \
        m = fmaxf(m, r[4]); m = fmaxf(m, r[5]); m = fmaxf(m, r[6]);           \
        m = fmaxf(m, r[7]); m = fmaxf(m, r[8]);                               \
        m = fmaxf(m, __shfl_xor_sync(0xffffffffu, m, 16));                    \
        m = fmaxf(m, __shfl_xor_sync(0xffffffffu, m, 8));                     \
        m = fmaxf(m, __shfl_xor_sync(0xffffffffu, m, 4));                     \
        m = fmaxf(m, __shfl_xor_sync(0xffffffffu, m, 2));                    \
        m = fmaxf(m, __shfl_xor_sync(0xffffffffu, m, 1));                    \
        int ex = (__float_as_int(m) >> 23) & 255;                             \
        int se = 60 - (ex - 127);                                             \
        se = (se > 127) ? 127 : ((se < -126) ? -126 : se);                    \
        const float sc = __int_as_float((se + 127) << 23);                    \
        r[0]*=sc; r[1]*=sc; r[2]*=sc; r[3]*=sc; r[4]*=sc;                     \
        r[5]*=sc; r[6]*=sc; r[7]*=sc; r[8]*=sc;                               \
        Esum += se;                                                           \
    } while (0)

    int t = 1;
    LOADSLOT(F0, P0, 1);
    LOADSLOT(F1, P1, 2);
    LOADSLOT(F2, P2, 3);
    LOADSLOT(F3, P3, 4);

    if (Tlen > 1) {
        for (;;) {
            STEP(F0, P0); LOADSLOT(F0, P0, t + 4);
            if (++t >= Tlen) break;
            if ((t & 7) == 0) RENORM();
            STEP(F1, P1); LOADSLOT(F1, P1, t + 4);
            if (++t >= Tlen) break;
            if ((t & 7) == 0) RENORM();
            STEP(F2, P2); LOADSLOT(F2, P2, t + 4);
            if (++t >= Tlen) break;
            if ((t & 7) == 0) RENORM();
            STEP(F3, P3); LOADSLOT(F3, P3, t + 4);
            if (++t >= Tlen) break;
            if ((t & 7) == 0) RENORM();
        }
    }

    __shared__ float fin[260];
#pragma unroll
    for (int j = 0; j < 8; j++) fin[lane * 8 + j] = r[j];
    if (lane == 31) fin[256] = r[8];
    __syncwarp();

    int cnt = 0;
#pragma unroll
    for (int i = 0; i < 4; i++) cnt += (tg[lane + i * 32] != 0);
#pragma unroll
    for (int o = 16; o > 0; o >>= 1) cnt += __shfl_xor_sync(0xffffffffu, cnt, o);
    const int sb = cnt;

    if (lane == 0) {
        const float e = fin[2 * sb - 1] + fin[2 * sb];
        out[b] = ((float)Esum * 0.6931471805599453f - logf(e)) / (float)sb;
    }
}

// ---------------------------------------------------------------------------
extern "C" void kernel_launch(void* const* d_in, const int* in_sizes, int n_in,
                              void* d_out, int out_size) {
    const int*   targets = (const int*)  d_in[0];
    const float* X       = (const float*)d_in[1];
    const int*   ilen    = (const int*)  d_in[2];
    const float* W1      = (const float*)d_in[3];
    const float* b1      = (const float*)d_in[4];
    const float* W2      = (const float*)d_in[5];
    const float* b2      = (const float*)d_in[6];
    float*       out     = (float*)d_out;

    const int M = BB * TT;  // 32768

    __nv_bfloat16 *xb, *w1t, *w2t, *hb;
    cudaGetSymbolAddress((void**)&xb,  g_Xb);
    cudaGetSymbolAddress((void**)&w1t, g_W1t);
    cudaGetSymbolAddress((void**)&w2t, g_W2t);
    cudaGetSymbolAddress((void**)&hb,  g_hb);

    f2bf_kernel<<<(M * HH) / (256 * 4), 256>>>(X, xb, M * HH);
    f2bfT_kernel<<<dim3(HH / 32, HH / 32), 256>>>(W1, w1t, HH, HH);
    f2bfT_kernel<<<dim3(VV / 32, HH / 32), 256>>>(W2, w2t, HH, VV);

    cudaFuncSetAttribute(gemm1_kernel, cudaFuncAttributeMaxDynamicSharedMemorySize, GSM);
    cudaFuncSetAttribute(gemm2_fused,  cudaFuncAttributeMaxDynamicSharedMemorySize, GSM);

    gemm1_kernel<<<dim3(HH / 128, M / 128), 256, GSM>>>(xb, w1t, b1, hb);
    gemm2_fused<<<dim3(VV / 128, M / 128), 256, GSM>>>(hb, w2t, b2, targets);

    lse_finish_kernel<<<M / 8, 256>>>();

    ctc_lin_kernel<<<BB, 32>>>(targets, ilen, out);
}